// round 2
// baseline (speedup 1.0000x reference)
#include <cuda_runtime.h>
#include <cstdint>

#define T_DIM 200
#define B_DIM 2048
#define I_DIM 128
#define H_DIM 128
#define K_LAB 4
#define S_TILE 64
#define GRID   512
#define BPC    4          // batches per CTA  (GRID * BPC == B_DIM)
#define THREADS 256
#define XROW   132        // padded x-tile row stride (floats): conflict-free A frags
#define BI     (B_DIM * I_DIM)

// ---- shared memory layout (float offsets) ----
#define SM_WP   0                          // 16nt*16kc*32lane*4 = 32768 (W frag pack)
#define SM_XS   (SM_WP + 32768)            // 64 * 132 = 8448
#define SM_HB   (SM_XS + S_TILE * XROW)    // 2 * 4 * 128 = 1024
#define SM_PB   (SM_HB + 1024)             // 4 * 64 * 4 = 1024
#define SM_CS   (SM_PB + 1024)             // 512
#define SM_X2   (SM_CS + 512)              // 512
#define SM_XL   (SM_X2 + 512)              // 512
#define SM_XM   (SM_XL + 512)              // 512
#define SM_PRE  (SM_XM + 512)              // 256
#define SM_TOT  (SM_PRE + 256)             // = 45568 floats = 182272 bytes

// W1 packed as B fragments: [nt(16)][kc(16)][lane(32)] -> (hi0, hi1, lo0, lo1)
__device__ float4 g_Wpack[16 * 16 * 32];

__device__ __forceinline__ uint32_t f2tf(float x) {
    uint32_t u;
    asm("cvt.rna.tf32.f32 %0, %1;" : "=r"(u) : "f"(x));
    return u;
}
__device__ __forceinline__ float sigf(float z) {
    float e, r;
    asm("ex2.approx.f32 %0, %1;" : "=f"(e) : "f"(-1.4426950408889634f * z));
    asm("rcp.approx.f32 %0, %1;" : "=f"(r) : "f"(1.0f + e));
    return r;
}
__device__ __forceinline__ void mma_tf32(float* c,
                                         uint32_t a0, uint32_t a1, uint32_t a2, uint32_t a3,
                                         uint32_t b0, uint32_t b1) {
    asm volatile(
        "mma.sync.aligned.m16n8k8.row.col.f32.tf32.tf32.f32 "
        "{%0,%1,%2,%3}, {%4,%5,%6,%7}, {%8,%9}, {%0,%1,%2,%3};"
        : "+f"(c[0]), "+f"(c[1]), "+f"(c[2]), "+f"(c[3])
        : "r"(a0), "r"(a1), "r"(a2), "r"(a3), "r"(b0), "r"(b1));
}

// ---------------- pack kernel: W1 -> tf32 hi/lo B-fragment layout ----------------
__global__ void pack_kernel(const float* __restrict__ w1_w) {
    int idx = blockIdx.x * blockDim.x + threadIdx.x;   // 0 .. 8191
    if (idx >= 16 * 16 * 32) return;
    int lane = idx & 31;
    int kc   = (idx >> 5) & 15;
    int nt   = idx >> 9;
    int k0 = kc * 8 + (lane & 3);
    int n  = nt * 8 + (lane >> 2);
    float wa = w1_w[n * I_DIM + k0];
    float wb = w1_w[n * I_DIM + k0 + 4];
    uint32_t h0 = f2tf(wa);
    uint32_t h1 = f2tf(wb);
    float l0 = wa - __uint_as_float(h0);
    float l1 = wb - __uint_as_float(h1);
    float4 v;
    v.x = __uint_as_float(h0);
    v.y = __uint_as_float(h1);
    v.z = __uint_as_float(f2tf(l0));
    v.w = __uint_as_float(f2tf(l1));
    g_Wpack[idx] = v;
}

// ---------------- main fused kernel ----------------
__global__ void __launch_bounds__(THREADS, 1)
fused_mma_kernel(const float* __restrict__ inputs,
                 const int*   __restrict__ lengths,
                 const float* __restrict__ w0,
                 const float* __restrict__ w1_b,
                 const float* __restrict__ w2_w,
                 const float* __restrict__ w3_w,
                 float* __restrict__ out)
{
    extern __shared__ float sm[];
    const int tid  = threadIdx.x;
    const int lane = tid & 31;
    const int wid  = tid >> 5;
    const int nh   = wid >> 1;          // h quarter: 32 h (4 n-tiles)
    const int mi2  = wid & 1;           // s half: 32 s (2 m-tiles)
    const int g    = lane >> 2;         // row group 0..7
    const int qc   = lane & 3;          // col class 0..3
    const int sbw  = mi2 * 32;

    // ---- copy packed W into smem (once per CTA) ----
    float4* wp4 = reinterpret_cast<float4*>(sm + SM_WP);
    for (int i = tid; i < 16 * 16 * 32; i += THREADS)
        wp4[i] = g_Wpack[i];

    // ---- hoist w0 / bias fragments (kernel-invariant) ----
    float w0r[4][2], b1r[4][2];
    #pragma unroll
    for (int nt = 0; nt < 4; nt++)
        #pragma unroll
        for (int c = 0; c < 2; c++) {
            int h = nh * 32 + nt * 8 + 2 * qc + c;
            w0r[nt][c] = w0[h];
            b1r[nt][c] = w1_b[h];
        }

    for (int bj = 0; bj < BPC; bj++) {
        const int b     = blockIdx.x + bj * GRID;
        const int len   = lengths[b];
        const int start = max(len - K_LAB, 0);
        const int nk    = min(len, K_LAB);

        __syncthreads();   // smem reuse guard (also covers wpack copy on bj==0)

        // ---- prefix sums / labeled snapshots (thread: i = tid&127, half = tid>>7) ----
        {
            const int i = tid & 127, half = tid >> 7;
            const float* ip = inputs + (size_t)b * I_DIM + i;
            float pa = 0.f, pb = 0.f, pc = 0.f, pd = 0.f;
            int s = half;
            for (; s + 8 <= start; s += 8) {
                pa += ip[(size_t)(s    ) * BI];
                pb += ip[(size_t)(s + 2) * BI];
                pc += ip[(size_t)(s + 4) * BI];
                pd += ip[(size_t)(s + 6) * BI];
            }
            for (; s < start; s += 2)
                pa += ip[(size_t)s * BI];
            sm[SM_PRE + half * 128 + i] = pa + pb + pc + pd;
            __syncthreads();
            if (half == 0) {
                float acc = sm[SM_PRE + i] + sm[SM_PRE + 128 + i];
                #pragma unroll
                for (int k = 0; k < K_LAB; k++) {
                    float xv = 0.f, mv = 0.f;
                    if (k < nk) {
                        xv = ip[(size_t)(start + k) * BI];
                        acc += xv;
                        mv = acc / (float)(start + k + 1);
                    }
                    sm[SM_XL + k * 128 + i] = xv;
                    sm[SM_XM + k * 128 + i] = mv;
                }
            }
        }
        __syncthreads();

        // ---- c[k][h] = x2_lab[k][h] + (w3 @ m)[k][h]  (thread: h = tid&127, k-pair = tid>>7) ----
        {
            const int h  = tid & 127;
            const int kh = (tid >> 7) * 2;
            float x2a = 0.f, x2b = 0.f, wma = 0.f, wmb = 0.f;
            const float4* w2r = reinterpret_cast<const float4*>(w2_w + h * I_DIM);
            const float4* w3r = reinterpret_cast<const float4*>(w3_w + h * I_DIM);
            #pragma unroll 4
            for (int i4 = 0; i4 < 32; i4++) {
                float4 a2 = w2r[i4];
                float4 a3 = w3r[i4];
                float4 xa = *reinterpret_cast<const float4*>(&sm[SM_XL + kh * 128 + i4 * 4]);
                float4 xb = *reinterpret_cast<const float4*>(&sm[SM_XL + (kh + 1) * 128 + i4 * 4]);
                float4 ma = *reinterpret_cast<const float4*>(&sm[SM_XM + kh * 128 + i4 * 4]);
                float4 mb = *reinterpret_cast<const float4*>(&sm[SM_XM + (kh + 1) * 128 + i4 * 4]);
                x2a += a2.x * xa.x + a2.y * xa.y + a2.z * xa.z + a2.w * xa.w;
                x2b += a2.x * xb.x + a2.y * xb.y + a2.z * xb.z + a2.w * xb.w;
                wma += a3.x * ma.x + a3.y * ma.y + a3.z * ma.z + a3.w * ma.w;
                wmb += a3.x * mb.x + a3.y * mb.y + a3.z * mb.z + a3.w * mb.w;
            }
            sm[SM_CS + kh * 128 + h]       = x2a + wma;
            sm[SM_CS + (kh + 1) * 128 + h] = x2b + wmb;
            sm[SM_X2 + kh * 128 + h]       = x2a;
            sm[SM_X2 + (kh + 1) * 128 + h] = x2b;
        }
        __syncthreads();

        // ---- hoist c fragments for this batch ----
        float ckr[K_LAB][4][2];
        #pragma unroll
        for (int k = 0; k < K_LAB; k++)
            #pragma unroll
            for (int nt = 0; nt < 4; nt++)
                #pragma unroll
                for (int c = 0; c < 2; c++)
                    ckr[k][nt][c] = sm[SM_CS + k * 128 + nh * 32 + nt * 8 + 2 * qc + c];

        float hacc[K_LAB][4][2];
        #pragma unroll
        for (int k = 0; k < K_LAB; k++)
            #pragma unroll
            for (int nt = 0; nt < 4; nt++) { hacc[k][nt][0] = 0.f; hacc[k][nt][1] = 0.f; }

        // ================= main tile loop =================
        for (int s0 = 0; s0 < len; s0 += S_TILE) {
            __syncthreads();   // previous tile's xs/pbuf reads complete

            // stage x tile [64 s][128 i] (zeros beyond len)
            {
                const int i = tid & 127, half = tid >> 7;
                #pragma unroll
                for (int j = 0; j < S_TILE / 2; j++) {
                    int ss = half + 2 * j;
                    int s  = s0 + ss;
                    float v = 0.f;
                    if (s < len)
                        v = inputs[(size_t)s * BI + (size_t)b * I_DIM + i];
                    sm[SM_XS + ss * XROW + i] = v;
                }
            }
            __syncthreads();

            // ---- 3-term tf32 MMA: x1 fragments ----
            float x1f[2][4][4];
            #pragma unroll
            for (int mt = 0; mt < 2; mt++)
                #pragma unroll
                for (int nt = 0; nt < 4; nt++)
                    #pragma unroll
                    for (int r = 0; r < 4; r++) x1f[mt][nt][r] = 0.f;

            #pragma unroll 4
            for (int kc = 0; kc < 16; kc++) {
                uint32_t ahi[2][4], alo[2][4];
                #pragma unroll
                for (int mt = 0; mt < 2; mt++) {
                    int rb = SM_XS + (sbw + mt * 16 + g) * XROW + kc * 8 + qc;
                    float a0 = sm[rb];
                    float a1 = sm[rb + 8 * XROW];
                    float a2 = sm[rb + 4];
                    float a3 = sm[rb + 8 * XROW + 4];
                    ahi[mt][0] = f2tf(a0); alo[mt][0] = f2tf(a0 - __uint_as_float(ahi[mt][0]));
                    ahi[mt][1] = f2tf(a1); alo[mt][1] = f2tf(a1 - __uint_as_float(ahi[mt][1]));
                    ahi[mt][2] = f2tf(a2); alo[mt][2] = f2tf(a2 - __uint_as_float(ahi[mt][2]));
                    ahi[mt][3] = f2tf(a3); alo[mt][3] = f2tf(a3 - __uint_as_float(ahi[mt][3]));
                }
                #pragma unroll
                for (int nt = 0; nt < 4; nt++) {
                    float4 bq = wp4[((nh * 4 + nt) * 16 + kc) * 32 + lane];
                    uint32_t bh0 = __float_as_uint(bq.x), bh1 = __float_as_uint(bq.y);
                    uint32_t bl0 = __float_as_uint(bq.z), bl1 = __float_as_uint(bq.w);
                    #pragma unroll
                    for (int mt = 0; mt < 2; mt++) {
                        mma_tf32(x1f[mt][nt], ahi[mt][0], ahi[mt][1], ahi[mt][2], ahi[mt][3], bh0, bh1);
                        mma_tf32(x1f[mt][nt], alo[mt][0], alo[mt][1], alo[mt][2], alo[mt][3], bh0, bh1);
                        mma_tf32(x1f[mt][nt], ahi[mt][0], ahi[mt][1], ahi[mt][2], ahi[mt][3], bl0, bl1);
                    }
                }
            }
            // add bias
            #pragma unroll
            for (int mt = 0; mt < 2; mt++)
                #pragma unroll
                for (int nt = 0; nt < 4; nt++)
                    #pragma unroll
                    for (int c = 0; c < 2; c++) {
                        x1f[mt][nt][c]     += b1r[nt][c];
                        x1f[mt][nt][2 + c] += b1r[nt][c];
                    }

            // ---- sigmoid + w0 partial sums ----
            float ps[K_LAB][2][2];
            #pragma unroll
            for (int k = 0; k < K_LAB; k++)
                #pragma unroll
                for (int mt = 0; mt < 2; mt++) { ps[k][mt][0] = 0.f; ps[k][mt][1] = 0.f; }

            #pragma unroll
            for (int k = 0; k < K_LAB; k++)
                #pragma unroll
                for (int mt = 0; mt < 2; mt++)
                    #pragma unroll
                    for (int nt = 0; nt < 4; nt++)
                        #pragma unroll
                        for (int c = 0; c < 2; c++) {
                            float z0 = x1f[mt][nt][c]     + ckr[k][nt][c];
                            float z1 = x1f[mt][nt][2 + c] + ckr[k][nt][c];
                            ps[k][mt][0] += w0r[nt][c] * sigf(z0);
                            ps[k][mt][1] += w0r[nt][c] * sigf(z1);
                        }

            // reduce over the 4 col-lanes (h within warp)
            #pragma unroll
            for (int k = 0; k < K_LAB; k++)
                #pragma unroll
                for (int mt = 0; mt < 2; mt++)
                    #pragma unroll
                    for (int r = 0; r < 2; r++) {
                        float v = ps[k][mt][r];
                        v += __shfl_xor_sync(0xffffffffu, v, 1);
                        v += __shfl_xor_sync(0xffffffffu, v, 2);
                        ps[k][mt][r] = v;
                    }

            if (qc == 0) {
                #pragma unroll
                for (int k = 0; k < K_LAB; k++)
                    #pragma unroll
                    for (int mt = 0; mt < 2; mt++) {
                        int sr = sbw + mt * 16 + g;
                        sm[SM_PB + (k * 64 + sr)     * 4 + nh] = ps[k][mt][0];
                        sm[SM_PB + (k * 64 + sr + 8) * 4 + nh] = ps[k][mt][1];
                    }
            }
            __syncthreads();

            // ---- read total p, mask, accumulate h ----
            const float4* pb4 = reinterpret_cast<const float4*>(sm + SM_PB);
            #pragma unroll
            for (int k = 0; k < K_LAB; k++) {
                const bool kv = (k < nk);
                const int  tk = start + k;
                #pragma unroll
                for (int mt = 0; mt < 2; mt++) {
                    int sr0 = sbw + mt * 16 + g;
                    float4 p0 = pb4[k * 64 + sr0];
                    float4 p1 = pb4[k * 64 + sr0 + 8];
                    float pt0 = (kv && (s0 + sr0)     <= tk) ? (p0.x + p0.y + p0.z + p0.w) : 0.f;
                    float pt1 = (kv && (s0 + sr0 + 8) <= tk) ? (p1.x + p1.y + p1.z + p1.w) : 0.f;
                    #pragma unroll
                    for (int nt = 0; nt < 4; nt++)
                        #pragma unroll
                        for (int c = 0; c < 2; c++)
                            hacc[k][nt][c] += pt0 * x1f[mt][nt][c] + pt1 * x1f[mt][nt][2 + c];
                }
            }
        }

        // ---- butterfly-reduce hacc over row groups ----
        #pragma unroll
        for (int k = 0; k < K_LAB; k++)
            #pragma unroll
            for (int nt = 0; nt < 4; nt++)
                #pragma unroll
                for (int c = 0; c < 2; c++) {
                    float v = hacc[k][nt][c];
                    v += __shfl_xor_sync(0xffffffffu, v, 4);
                    v += __shfl_xor_sync(0xffffffffu, v, 8);
                    v += __shfl_xor_sync(0xffffffffu, v, 16);
                    hacc[k][nt][c] = v;
                }

        __syncthreads();
        if (g == 0) {   // lanes 0..3 (qc == lane)
            #pragma unroll
            for (int k = 0; k < K_LAB; k++)
                #pragma unroll
                for (int nt = 0; nt < 4; nt++)
                    #pragma unroll
                    for (int c = 0; c < 2; c++)
                        sm[SM_HB + (mi2 * 4 + k) * 128 + nh * 32 + nt * 8 + 2 * qc + c] = hacc[k][nt][c];
        }
        __syncthreads();

        // ---- final output: combine s-halves + x2, mask invalid k ----
        #pragma unroll
        for (int j = 0; j < 2; j++) {
            int idx = tid + j * 256;        // 0..511
            int k = idx >> 7, h = idx & 127;
            float v = 0.f;
            if (k < nk)
                v = sm[SM_HB + k * 128 + h] + sm[SM_HB + (4 + k) * 128 + h]
                  + sm[SM_X2 + k * 128 + h];
            out[(size_t)b * (K_LAB * H_DIM) + idx] = v;
        }
    }
}

extern "C" void kernel_launch(void* const* d_in, const int* in_sizes, int n_in,
                              void* d_out, int out_size)
{
    // input order: inputs, lengths, [label_len], w0, w1_w, w1_b, w2_w, w3_w
    const int base = (n_in >= 8) ? 3 : 2;
    const float* inputs  = (const float*)d_in[0];
    const int*   lengths = (const int*)d_in[1];
    const float* w0   = (const float*)d_in[base + 0];
    const float* w1_w = (const float*)d_in[base + 1];
    const float* w1_b = (const float*)d_in[base + 2];
    const float* w2_w = (const float*)d_in[base + 3];
    const float* w3_w = (const float*)d_in[base + 4];
    float* out = (float*)d_out;

    pack_kernel<<<32, 256>>>(w1_w);

    const size_t smem_bytes = (size_t)SM_TOT * sizeof(float);
    static int smem_set = 0;
    if (!smem_set) {
        cudaFuncSetAttribute(fused_mma_kernel,
                             cudaFuncAttributeMaxDynamicSharedMemorySize,
                             (int)smem_bytes);
        smem_set = 1;
    }
    fused_mma_kernel<<<GRID, THREADS, smem_bytes>>>(inputs, lengths, w0, w1_b,
                                                    w2_w, w3_w, out);
}

// round 3
// speedup vs baseline: 1.0152x; 1.0152x over previous
#include <cuda_runtime.h>
#include <cstdint>

#define T_DIM 200
#define B_DIM 2048
#define I_DIM 128
#define H_DIM 128
#define K_LAB 4
#define S_TILE 64
#define GRID   1024
#define BPC    2
#define THREADS 512
#define XP     68            // pair-row stride (u32): conflict-free A-frag reads
#define BI     (B_DIM * I_DIM)

// ---- shared memory layout (4-byte word offsets) ----
#define SM_WP   0                      // 16*8*32 uint4 = 16384 words (64 KB W pack)
#define SM_XH   (SM_WP + 16384)        // 64*XP = 4352  (x hi, bf16x2 pairs)
#define SM_XLO  (SM_XH + 64*XP)        // 4352          (x lo)
#define SM_PB   (SM_XLO + 64*XP)       // 4*64*4 = 1024
#define SM_CS   (SM_PB + 1024)         // 512
#define SM_X2   (SM_CS + 512)          // 512
#define SM_XL   (SM_X2 + 512)          // 512
#define SM_XM   (SM_XL + 512)          // 512
#define SM_PRE  (SM_XM + 512)          // 512
#define SM_HB   (SM_PRE + 512)         // 4mi*4k*128 = 2048
#define SM_TOT  (SM_HB + 2048)         // 30720 words = 122880 B

// W1 packed as bf16 B fragments: [nt(16)][kc(8)][lane(32)] -> (bh0,bh1,bl0,bl1)
__device__ uint4 g_Wpack[16 * 8 * 32];

__device__ __forceinline__ uint32_t pack_bf16x2(float e_even, float e_odd) {
    // low 16 = bf16(e_even) (even k), high 16 = bf16(e_odd)
    uint32_t r;
    asm("cvt.rn.bf16x2.f32 %0, %1, %2;" : "=r"(r) : "f"(e_odd), "f"(e_even));
    return r;
}
__device__ __forceinline__ float bf_lo(uint32_t u) { return __uint_as_float(u << 16); }
__device__ __forceinline__ float bf_hi(uint32_t u) { return __uint_as_float(u & 0xffff0000u); }

__device__ __forceinline__ float sigf(float z) {
    float e, r;
    asm("ex2.approx.f32 %0, %1;" : "=f"(e) : "f"(-1.4426950408889634f * z));
    asm("rcp.approx.f32 %0, %1;" : "=f"(r) : "f"(1.0f + e));
    return r;
}
__device__ __forceinline__ void mma_bf16(float* c,
                                         uint32_t a0, uint32_t a1, uint32_t a2, uint32_t a3,
                                         uint32_t b0, uint32_t b1) {
    asm volatile(
        "mma.sync.aligned.m16n8k16.row.col.f32.bf16.bf16.f32 "
        "{%0,%1,%2,%3}, {%4,%5,%6,%7}, {%8,%9}, {%0,%1,%2,%3};"
        : "+f"(c[0]), "+f"(c[1]), "+f"(c[2]), "+f"(c[3])
        : "r"(a0), "r"(a1), "r"(a2), "r"(a3), "r"(b0), "r"(b1));
}

// ---------------- pack kernel: W1 -> bf16 hi/lo B-fragment layout ----------------
__global__ void pack_kernel(const float* __restrict__ w1_w) {
    int idx = blockIdx.x * blockDim.x + threadIdx.x;      // [nt(16)][kc(8)][lane(32)]
    if (idx >= 16 * 8 * 32) return;
    int lane = idx & 31;
    int kc   = (idx >> 5) & 7;
    int nt   = idx >> 8;
    int n  = nt * 8 + (lane >> 2);
    int k0 = kc * 16 + 2 * (lane & 3);
    const float* wr = w1_w + n * I_DIM;
    float w00 = wr[k0], w01 = wr[k0 + 1], w10 = wr[k0 + 8], w11 = wr[k0 + 9];
    uint32_t bh0 = pack_bf16x2(w00, w01);
    uint32_t bh1 = pack_bf16x2(w10, w11);
    float r00 = w00 - bf_lo(bh0), r01 = w01 - bf_hi(bh0);
    float r10 = w10 - bf_lo(bh1), r11 = w11 - bf_hi(bh1);
    uint4 v;
    v.x = bh0; v.y = bh1;
    v.z = pack_bf16x2(r00, r01);
    v.w = pack_bf16x2(r10, r11);
    g_Wpack[idx] = v;
}

// ---------------- main fused kernel ----------------
__global__ void __launch_bounds__(THREADS, 1)
fused_bf16_kernel(const float* __restrict__ inputs,
                  const int*   __restrict__ lengths,
                  const float* __restrict__ w0,
                  const float* __restrict__ w1_b,
                  const float* __restrict__ w2_w,
                  const float* __restrict__ w3_w,
                  float* __restrict__ out)
{
    extern __shared__ float sm[];
    uint32_t* smu = reinterpret_cast<uint32_t*>(sm);

    const int tid  = threadIdx.x;
    const int lane = tid & 31;
    const int wid  = tid >> 5;
    const int nh   = wid & 3;        // h quarter (32 h = 4 n-tiles)
    const int mi   = wid >> 2;       // s quarter (16 s = 1 m-tile)
    const int g    = lane >> 2;      // row group 0..7
    const int qc   = lane & 3;       // col class 0..3
    const int sbw  = mi * 16;

    // ---- copy packed W into smem (once per CTA) ----
    uint4* wp4 = reinterpret_cast<uint4*>(smu + SM_WP);
    for (int i = tid; i < 16 * 8 * 32; i += THREADS)
        wp4[i] = g_Wpack[i];

    // ---- hoist w0 / bias fragments ----
    float w0r[4][2], b1r[4][2];
    #pragma unroll
    for (int nt = 0; nt < 4; nt++)
        #pragma unroll
        for (int c = 0; c < 2; c++) {
            int h = nh * 32 + nt * 8 + 2 * qc + c;
            w0r[nt][c] = w0[h];
            b1r[nt][c] = w1_b[h];
        }

    for (int bj = 0; bj < BPC; bj++) {
        const int b     = blockIdx.x + bj * GRID;
        const int len   = lengths[b];
        const int start = max(len - K_LAB, 0);
        const int nk    = min(len, K_LAB);

        __syncthreads();

        // ---- prefix sums (4-way split over s) ----
        {
            const int i = tid & 127;
            const int q = tid >> 7;
            const float* ip = inputs + (size_t)b * I_DIM + i;
            float pa = 0.f, pb_ = 0.f;
            int s = q;
            for (; s + 8 <= start; s += 8) {
                pa  += ip[(size_t)s * BI];
                pb_ += ip[(size_t)(s + 4) * BI];
            }
            for (; s < start; s += 4)
                pa += ip[(size_t)s * BI];
            sm[SM_PRE + q * 128 + i] = pa + pb_;
            __syncthreads();
            if (q == 0) {
                float acc = sm[SM_PRE + i] + sm[SM_PRE + 128 + i]
                          + sm[SM_PRE + 256 + i] + sm[SM_PRE + 384 + i];
                #pragma unroll
                for (int k = 0; k < K_LAB; k++) {
                    float xv = 0.f, mv = 0.f;
                    if (k < nk) {
                        xv = ip[(size_t)(start + k) * BI];
                        acc += xv;
                        mv = acc / (float)(start + k + 1);
                    }
                    sm[SM_XL + k * 128 + i] = xv;
                    sm[SM_XM + k * 128 + i] = mv;
                }
            }
        }
        __syncthreads();

        // ---- c[k][h] = x2_lab + w3 @ m  (thread: h = tid&127, k = tid>>7) ----
        {
            const int h = tid & 127;
            const int k = tid >> 7;
            float x2v = 0.f, wmv = 0.f;
            const float4* w2r = reinterpret_cast<const float4*>(w2_w + h * I_DIM);
            const float4* w3r = reinterpret_cast<const float4*>(w3_w + h * I_DIM);
            #pragma unroll 8
            for (int i4 = 0; i4 < 32; i4++) {
                float4 a2 = w2r[i4];
                float4 a3 = w3r[i4];
                float4 xl = *reinterpret_cast<const float4*>(&sm[SM_XL + k * 128 + i4 * 4]);
                float4 xm = *reinterpret_cast<const float4*>(&sm[SM_XM + k * 128 + i4 * 4]);
                x2v += a2.x * xl.x + a2.y * xl.y + a2.z * xl.z + a2.w * xl.w;
                wmv += a3.x * xm.x + a3.y * xm.y + a3.z * xm.z + a3.w * xm.w;
            }
            sm[SM_CS + k * 128 + h] = x2v + wmv;
            sm[SM_X2 + k * 128 + h] = x2v;
        }

        float hacc[K_LAB][4][2];
        #pragma unroll
        for (int k = 0; k < K_LAB; k++)
            #pragma unroll
            for (int nt = 0; nt < 4; nt++) { hacc[k][nt][0] = 0.f; hacc[k][nt][1] = 0.f; }

        // ================= main tile loop =================
        for (int s0 = 0; s0 < len; s0 += S_TILE) {
            __syncthreads();   // protect xh/xlo/pbuf from previous iteration

            // ---- stage x tile -> bf16 hi/lo pairs (converted once) ----
            {
                const int s   = tid >> 3;
                const int seg = tid & 7;
                const int gs  = s0 + s;
                const bool vld = (gs < len);
                const float4* src = reinterpret_cast<const float4*>(
                    inputs + (size_t)gs * BI + (size_t)b * I_DIM + seg * 16);
                #pragma unroll
                for (int j = 0; j < 4; j++) {
                    float4 x = vld ? src[j] : make_float4(0.f, 0.f, 0.f, 0.f);
                    uint32_t h0 = pack_bf16x2(x.x, x.y);
                    uint32_t h1 = pack_bf16x2(x.z, x.w);
                    float r0 = x.x - bf_lo(h0), r1 = x.y - bf_hi(h0);
                    float r2 = x.z - bf_lo(h1), r3 = x.w - bf_hi(h1);
                    uint32_t l0 = pack_bf16x2(r0, r1);
                    uint32_t l1 = pack_bf16x2(r2, r3);
                    int p = s * XP + seg * 8 + j * 2;
                    smu[SM_XH + p]      = h0;
                    smu[SM_XH + p + 1]  = h1;
                    smu[SM_XLO + p]     = l0;
                    smu[SM_XLO + p + 1] = l1;
                }
            }
            __syncthreads();

            // ---- 3-term bf16 MMA: x1 fragments (16s x 32h per warp) ----
            float x1f[4][4];
            #pragma unroll
            for (int nt = 0; nt < 4; nt++)
                #pragma unroll
                for (int r = 0; r < 4; r++) x1f[nt][r] = 0.f;

            #pragma unroll
            for (int kc = 0; kc < 8; kc++) {
                const int rb = (sbw + g) * XP + kc * 8 + qc;
                uint32_t ah0 = smu[SM_XH + rb];
                uint32_t ah1 = smu[SM_XH + rb + 8 * XP];
                uint32_t ah2 = smu[SM_XH + rb + 4];
                uint32_t ah3 = smu[SM_XH + rb + 8 * XP + 4];
                uint32_t al0 = smu[SM_XLO + rb];
                uint32_t al1 = smu[SM_XLO + rb + 8 * XP];
                uint32_t al2 = smu[SM_XLO + rb + 4];
                uint32_t al3 = smu[SM_XLO + rb + 8 * XP + 4];
                #pragma unroll
                for (int nt = 0; nt < 4; nt++) {
                    uint4 bq = wp4[((nh * 4 + nt) * 8 + kc) * 32 + lane];
                    mma_bf16(x1f[nt], ah0, ah1, ah2, ah3, bq.x, bq.y);  // hi*hi
                    mma_bf16(x1f[nt], al0, al1, al2, al3, bq.x, bq.y);  // lo*hi
                    mma_bf16(x1f[nt], ah0, ah1, ah2, ah3, bq.z, bq.w);  // hi*lo
                }
            }
            #pragma unroll
            for (int nt = 0; nt < 4; nt++) {
                x1f[nt][0] += b1r[nt][0];
                x1f[nt][1] += b1r[nt][1];
                x1f[nt][2] += b1r[nt][0];
                x1f[nt][3] += b1r[nt][1];
            }

            // ---- sigmoid + w0 partial sums (skip k's fully beyond causal bound) ----
            #pragma unroll
            for (int k = 0; k < K_LAB; k++) {
                const int tk = start + k;
                if (k < nk && s0 + sbw <= tk) {          // block/warp-uniform
                    float ps0 = 0.f, ps1 = 0.f;
                    #pragma unroll
                    for (int nt = 0; nt < 4; nt++) {
                        float c0 = sm[SM_CS + k * 128 + nh * 32 + nt * 8 + 2 * qc];
                        float c1 = sm[SM_CS + k * 128 + nh * 32 + nt * 8 + 2 * qc + 1];
                        ps0 += w0r[nt][0] * sigf(x1f[nt][0] + c0)
                             + w0r[nt][1] * sigf(x1f[nt][1] + c1);
                        ps1 += w0r[nt][0] * sigf(x1f[nt][2] + c0)
                             + w0r[nt][1] * sigf(x1f[nt][3] + c1);
                    }
                    ps0 += __shfl_xor_sync(0xffffffffu, ps0, 1);
                    ps0 += __shfl_xor_sync(0xffffffffu, ps0, 2);
                    ps1 += __shfl_xor_sync(0xffffffffu, ps1, 1);
                    ps1 += __shfl_xor_sync(0xffffffffu, ps1, 2);
                    if (qc == 0) {
                        sm[SM_PB + (k * 64 + sbw + g) * 4 + nh]     = ps0;
                        sm[SM_PB + (k * 64 + sbw + g + 8) * 4 + nh] = ps1;
                    }
                }
            }
            __syncthreads();

            // ---- read total p, mask, accumulate h ----
            const float4* pb4 = reinterpret_cast<const float4*>(sm + SM_PB);
            #pragma unroll
            for (int k = 0; k < K_LAB; k++) {
                const int tk = start + k;
                if (k < nk && s0 + sbw <= tk) {
                    float4 p0 = pb4[k * 64 + sbw + g];
                    float4 p1 = pb4[k * 64 + sbw + g + 8];
                    float pt0 = (s0 + sbw + g     <= tk) ? (p0.x + p0.y + p0.z + p0.w) : 0.f;
                    float pt1 = (s0 + sbw + g + 8 <= tk) ? (p1.x + p1.y + p1.z + p1.w) : 0.f;
                    #pragma unroll
                    for (int nt = 0; nt < 4; nt++) {
                        hacc[k][nt][0] += pt0 * x1f[nt][0] + pt1 * x1f[nt][2];
                        hacc[k][nt][1] += pt0 * x1f[nt][1] + pt1 * x1f[nt][3];
                    }
                }
            }
        }

        // ---- reduce hacc over row groups, stash per-mi partials ----
        #pragma unroll
        for (int k = 0; k < K_LAB; k++)
            #pragma unroll
            for (int nt = 0; nt < 4; nt++)
                #pragma unroll
                for (int c = 0; c < 2; c++) {
                    float v = hacc[k][nt][c];
                    v += __shfl_xor_sync(0xffffffffu, v, 4);
                    v += __shfl_xor_sync(0xffffffffu, v, 8);
                    v += __shfl_xor_sync(0xffffffffu, v, 16);
                    if (g == 0)
                        sm[SM_HB + (mi * 4 + k) * 128 + nh * 32 + nt * 8 + 2 * qc + c] = v;
                }
        __syncthreads();

        // ---- final output ----
        {
            const int k = tid >> 7;
            const int h = tid & 127;
            float v = 0.f;
            if (k < nk)
                v = sm[SM_HB + (0 * 4 + k) * 128 + h]
                  + sm[SM_HB + (1 * 4 + k) * 128 + h]
                  + sm[SM_HB + (2 * 4 + k) * 128 + h]
                  + sm[SM_HB + (3 * 4 + k) * 128 + h]
                  + sm[SM_X2 + k * 128 + h];
            out[(size_t)b * (K_LAB * H_DIM) + tid] = v;
        }
    }
}

extern "C" void kernel_launch(void* const* d_in, const int* in_sizes, int n_in,
                              void* d_out, int out_size)
{
    // input order: inputs, lengths, [label_len], w0, w1_w, w1_b, w2_w, w3_w
    const int base = (n_in >= 8) ? 3 : 2;
    const float* inputs  = (const float*)d_in[0];
    const int*   lengths = (const int*)d_in[1];
    const float* w0   = (const float*)d_in[base + 0];
    const float* w1_w = (const float*)d_in[base + 1];
    const float* w1_b = (const float*)d_in[base + 2];
    const float* w2_w = (const float*)d_in[base + 3];
    const float* w3_w = (const float*)d_in[base + 4];
    float* out = (float*)d_out;

    pack_kernel<<<16, 256>>>(w1_w);

    const size_t smem_bytes = (size_t)SM_TOT * sizeof(float);
    cudaFuncSetAttribute(fused_bf16_kernel,
                         cudaFuncAttributeMaxDynamicSharedMemorySize,
                         (int)smem_bytes);
    fused_bf16_kernel<<<GRID, THREADS, smem_bytes>>>(inputs, lengths, w0, w1_b,
                                                     w2_w, w3_w, out);
}

// round 4
// speedup vs baseline: 1.7816x; 1.7549x over previous
#include <cuda_runtime.h>
#include <cstdint>

#define T_DIM 200
#define B_DIM 2048
#define I_DIM 128
#define H_DIM 128
#define K_LAB 4
#define S_TILE 32
#define GRID   2048
#define THREADS 256
#define XP     68             // pair-row stride (u32 words): conflict-free A-frag reads
#define BI     (B_DIM * I_DIM)

// ---- shared memory layout (4-byte word offsets) ----
#define SM_WP   0              // 16*8*32 uint4 = 16384 words (64 KB W pack)
#define SM_XB   16384          // two staging buffers, each XH(2176)+XLO(2176)
#define BUFW    4352
#define SM_PB   (SM_XB + 2*BUFW)   // 25088: 4k*32row*4nh = 512
#define SM_CS   (SM_PB + 512)      // 512
#define SM_X2   (SM_CS + 512)      // 512
#define SM_XL   (SM_X2 + 512)      // 512
#define SM_XM   (SM_XL + 512)      // 512
#define SM_PRE  (SM_XM + 512)      // 256
#define SM_HB   SM_XB              // reused after tile loop: 2mi*4k*128 = 1024
#define SM_TOT  (SM_PRE + 256)     // 27904 words = 111616 B

// W1 packed as bf16 B fragments: [nt(16)][kc(8)][lane(32)] -> (bh0,bh1,bl0,bl1)
__device__ uint4 g_Wpack[16 * 8 * 32];

__device__ __forceinline__ uint32_t pack_bf16x2(float e_even, float e_odd) {
    uint32_t r;
    asm("cvt.rn.bf16x2.f32 %0, %1, %2;" : "=r"(r) : "f"(e_odd), "f"(e_even));
    return r;
}
__device__ __forceinline__ float bf_lo(uint32_t u) { return __uint_as_float(u << 16); }
__device__ __forceinline__ float bf_hi(uint32_t u) { return __uint_as_float(u & 0xffff0000u); }

__device__ __forceinline__ float tanhf_fast(float z) {
    float t;
    asm("tanh.approx.f32 %0, %1;" : "=f"(t) : "f"(z));
    return t;
}
__device__ __forceinline__ void mma_bf16(float* c,
                                         uint32_t a0, uint32_t a1, uint32_t a2, uint32_t a3,
                                         uint32_t b0, uint32_t b1) {
    asm volatile(
        "mma.sync.aligned.m16n8k16.row.col.f32.bf16.bf16.f32 "
        "{%0,%1,%2,%3}, {%4,%5,%6,%7}, {%8,%9}, {%0,%1,%2,%3};"
        : "+f"(c[0]), "+f"(c[1]), "+f"(c[2]), "+f"(c[3])
        : "r"(a0), "r"(a1), "r"(a2), "r"(a3), "r"(b0), "r"(b1));
}

// ---------------- pack kernel: W1 -> bf16 hi/lo B-fragment layout ----------------
__global__ void pack_kernel(const float* __restrict__ w1_w) {
    int idx = blockIdx.x * blockDim.x + threadIdx.x;      // [nt(16)][kc(8)][lane(32)]
    if (idx >= 16 * 8 * 32) return;
    int lane = idx & 31;
    int kc   = (idx >> 5) & 7;
    int nt   = idx >> 8;
    int n  = nt * 8 + (lane >> 2);
    int k0 = kc * 16 + 2 * (lane & 3);
    const float* wr = w1_w + n * I_DIM;
    float w00 = wr[k0], w01 = wr[k0 + 1], w10 = wr[k0 + 8], w11 = wr[k0 + 9];
    uint32_t bh0 = pack_bf16x2(w00, w01);
    uint32_t bh1 = pack_bf16x2(w10, w11);
    float r00 = w00 - bf_lo(bh0), r01 = w01 - bf_hi(bh0);
    float r10 = w10 - bf_lo(bh1), r11 = w11 - bf_hi(bh1);
    uint4 v;
    v.x = bh0; v.y = bh1;
    v.z = pack_bf16x2(r00, r01);
    v.w = pack_bf16x2(r10, r11);
    g_Wpack[idx] = v;
}

// ---------------- main fused kernel ----------------
__global__ void __launch_bounds__(THREADS, 2)
fused_db_kernel(const float* __restrict__ inputs,
                const int*   __restrict__ lengths,
                const float* __restrict__ w0,
                const float* __restrict__ w1_b,
                const float* __restrict__ w2_w,
                const float* __restrict__ w3_w,
                float* __restrict__ out)
{
    extern __shared__ float sm[];
    uint32_t* smu = reinterpret_cast<uint32_t*>(sm);

    const int tid  = threadIdx.x;
    const int lane = tid & 31;
    const int wid  = tid >> 5;
    const int nh   = wid & 3;        // h quarter (32 h = 4 n-tiles)
    const int mi   = wid >> 2;       // s half of tile (16 s)
    const int g    = lane >> 2;      // row group 0..7
    const int qc   = lane & 3;       // col class 0..3
    const int sbw  = mi * 16;

    const int b     = blockIdx.x;
    const int len   = lengths[b];
    const int start = max(len - K_LAB, 0);
    const int nk    = min(len, K_LAB);

    // ---- copy packed W into smem ----
    uint4* wp4 = reinterpret_cast<uint4*>(smu + SM_WP);
    #pragma unroll
    for (int i = 0; i < 16; i++)
        wp4[tid + i * THREADS] = g_Wpack[tid + i * THREADS];

    // ---- hoist w0 (pre-halved) / bias fragments ----
    float w0h[4][2], b1r[4][2];
    float w0s = 0.f;
    #pragma unroll
    for (int nt = 0; nt < 4; nt++)
        #pragma unroll
        for (int c = 0; c < 2; c++) {
            int h = nh * 32 + nt * 8 + 2 * qc + c;
            w0h[nt][c] = 0.5f * w0[h];
            w0s += w0h[nt][c];
            b1r[nt][c] = w1_b[h];
        }

    // ---- prefix partial sums: i = tid&127, parity q = tid>>7, MLP-8 ----
    {
        const int i = tid & 127;
        const int q = tid >> 7;
        const float* ip = inputs + (size_t)b * I_DIM + i;
        float a0 = 0.f, a1 = 0.f, a2 = 0.f, a3 = 0.f;
        int s = q;
        for (; s + 16 <= start; s += 16) {
            float v0 = ip[(size_t)(s     ) * BI];
            float v1 = ip[(size_t)(s +  2) * BI];
            float v2 = ip[(size_t)(s +  4) * BI];
            float v3 = ip[(size_t)(s +  6) * BI];
            float v4 = ip[(size_t)(s +  8) * BI];
            float v5 = ip[(size_t)(s + 10) * BI];
            float v6 = ip[(size_t)(s + 12) * BI];
            float v7 = ip[(size_t)(s + 14) * BI];
            a0 += v0 + v4; a1 += v1 + v5; a2 += v2 + v6; a3 += v3 + v7;
        }
        for (; s < start; s += 2)
            a0 += ip[(size_t)s * BI];
        sm[SM_PRE + q * 128 + i] = (a0 + a1) + (a2 + a3);
    }
    __syncthreads();

    // ---- labeled snapshots (q == 0 threads) ----
    {
        const int i = tid & 127;
        if (tid < 128) {
            const float* ip = inputs + (size_t)b * I_DIM + i;
            float acc = sm[SM_PRE + i] + sm[SM_PRE + 128 + i];
            #pragma unroll
            for (int k = 0; k < K_LAB; k++) {
                float xv = 0.f, mv = 0.f;
                if (k < nk) {
                    xv = ip[(size_t)(start + k) * BI];
                    acc += xv;
                    mv = acc / (float)(start + k + 1);
                }
                sm[SM_XL + k * 128 + i] = xv;
                sm[SM_XM + k * 128 + i] = mv;
            }
        }
    }
    __syncthreads();

    const int n_tiles = (len + S_TILE - 1) >> 5;

    // ---- issue prologue staging loads for tile 0 ----
    const int srow = tid >> 3;            // local row 0..31
    const int f4c  = tid & 7;             // 4 consecutive float4s
    float4 stg[4];
    {
        const bool vld = (srow < len);    // tile 0: s = srow
        const float4* src = reinterpret_cast<const float4*>(
            inputs + (size_t)srow * BI + (size_t)b * I_DIM + f4c * 16);
        #pragma unroll
        for (int jj = 0; jj < 4; jj++)
            stg[jj] = vld ? src[jj] : make_float4(0.f, 0.f, 0.f, 0.f);
    }

    // ---- c[k][h] = x2_lab + w3 @ m  (h = tid&127, k in {kq, kq+2}) ----
    {
        const int h  = tid & 127;
        const int kq = tid >> 7;
        float x2a = 0.f, x2b = 0.f, wma = 0.f, wmb = 0.f;
        const float4* w2r = reinterpret_cast<const float4*>(w2_w + h * I_DIM);
        const float4* w3r = reinterpret_cast<const float4*>(w3_w + h * I_DIM);
        #pragma unroll 4
        for (int i4 = 0; i4 < 32; i4++) {
            float4 a2 = w2r[i4];
            float4 a3 = w3r[i4];
            float4 xa = *reinterpret_cast<const float4*>(&sm[SM_XL + kq * 128 + i4 * 4]);
            float4 xb = *reinterpret_cast<const float4*>(&sm[SM_XL + (kq + 2) * 128 + i4 * 4]);
            float4 ma = *reinterpret_cast<const float4*>(&sm[SM_XM + kq * 128 + i4 * 4]);
            float4 mb = *reinterpret_cast<const float4*>(&sm[SM_XM + (kq + 2) * 128 + i4 * 4]);
            x2a += a2.x * xa.x + a2.y * xa.y + a2.z * xa.z + a2.w * xa.w;
            x2b += a2.x * xb.x + a2.y * xb.y + a2.z * xb.z + a2.w * xb.w;
            wma += a3.x * ma.x + a3.y * ma.y + a3.z * ma.z + a3.w * ma.w;
            wmb += a3.x * mb.x + a3.y * mb.y + a3.z * mb.z + a3.w * mb.w;
        }
        sm[SM_CS + kq * 128 + h]       = x2a + wma;
        sm[SM_CS + (kq + 2) * 128 + h] = x2b + wmb;
        sm[SM_X2 + kq * 128 + h]       = x2a;
        sm[SM_X2 + (kq + 2) * 128 + h] = x2b;
    }

    // ---- store prologue staged tile 0 into buffer 0 ----
    {
        uint32_t* xh = smu + SM_XB;
        uint32_t* xl = smu + SM_XB + 2176;
        #pragma unroll
        for (int jj = 0; jj < 4; jj++) {
            float4 x = stg[jj];
            uint32_t h0 = pack_bf16x2(x.x, x.y);
            uint32_t h1 = pack_bf16x2(x.z, x.w);
            uint32_t l0 = pack_bf16x2(x.x - bf_lo(h0), x.y - bf_hi(h0));
            uint32_t l1 = pack_bf16x2(x.z - bf_lo(h1), x.w - bf_hi(h1));
            int p = srow * XP + (f4c * 4 + jj) * 2;
            *reinterpret_cast<uint2*>(xh + p) = make_uint2(h0, h1);
            *reinterpret_cast<uint2*>(xl + p) = make_uint2(l0, l1);
        }
    }
    __syncthreads();

    float hacc[K_LAB][4][2];
    #pragma unroll
    for (int k = 0; k < K_LAB; k++)
        #pragma unroll
        for (int nt = 0; nt < 4; nt++) { hacc[k][nt][0] = 0.f; hacc[k][nt][1] = 0.f; }

    // ================= main tile loop (double-buffered) =================
    for (int t = 0; t < n_tiles; t++) {
        const int s0  = t * S_TILE;
        const int buf = t & 1;
        const bool have_next = (t + 1 < n_tiles);

        // issue next tile's loads NOW (latency hidden behind compute below)
        if (have_next) {
            const int gs = s0 + S_TILE + srow;
            const bool vld = (gs < len);
            const float4* src = reinterpret_cast<const float4*>(
                inputs + (size_t)gs * BI + (size_t)b * I_DIM + f4c * 16);
            #pragma unroll
            for (int jj = 0; jj < 4; jj++)
                stg[jj] = vld ? src[jj] : make_float4(0.f, 0.f, 0.f, 0.f);
        }

        // ---- 3-term bf16 MMA on current buffer ----
        const uint32_t* xh = smu + SM_XB + buf * BUFW;
        const uint32_t* xl = xh + 2176;

        float x1f[4][4];
        #pragma unroll
        for (int nt = 0; nt < 4; nt++)
            #pragma unroll
            for (int r = 0; r < 4; r++) x1f[nt][r] = 0.f;

        #pragma unroll
        for (int kc = 0; kc < 8; kc++) {
            const int rb = (sbw + g) * XP + kc * 8 + qc;
            uint32_t ah0 = xh[rb];
            uint32_t ah1 = xh[rb + 8 * XP];
            uint32_t ah2 = xh[rb + 4];
            uint32_t ah3 = xh[rb + 8 * XP + 4];
            uint32_t al0 = xl[rb];
            uint32_t al1 = xl[rb + 8 * XP];
            uint32_t al2 = xl[rb + 4];
            uint32_t al3 = xl[rb + 8 * XP + 4];
            #pragma unroll
            for (int nt = 0; nt < 4; nt++) {
                uint4 bq = wp4[((nh * 4 + nt) * 8 + kc) * 32 + lane];
                mma_bf16(x1f[nt], ah0, ah1, ah2, ah3, bq.x, bq.y);
                mma_bf16(x1f[nt], al0, al1, al2, al3, bq.x, bq.y);
                mma_bf16(x1f[nt], ah0, ah1, ah2, ah3, bq.z, bq.w);
            }
        }
        #pragma unroll
        for (int nt = 0; nt < 4; nt++) {
            x1f[nt][0] += b1r[nt][0];
            x1f[nt][1] += b1r[nt][1];
            x1f[nt][2] += b1r[nt][0];
            x1f[nt][3] += b1r[nt][1];
        }

        // ---- sigmoid (tanh) + w0 partial sums ----
        #pragma unroll
        for (int k = 0; k < K_LAB; k++) {
            const int tk = start + k;
            if (k < nk && s0 + sbw <= tk) {
                float ps0 = w0s, ps1 = w0s;
                #pragma unroll
                for (int nt = 0; nt < 4; nt++) {
                    float c0 = sm[SM_CS + k * 128 + nh * 32 + nt * 8 + 2 * qc];
                    float c1 = sm[SM_CS + k * 128 + nh * 32 + nt * 8 + 2 * qc + 1];
                    ps0 += w0h[nt][0] * tanhf_fast(0.5f * (x1f[nt][0] + c0))
                         + w0h[nt][1] * tanhf_fast(0.5f * (x1f[nt][1] + c1));
                    ps1 += w0h[nt][0] * tanhf_fast(0.5f * (x1f[nt][2] + c0))
                         + w0h[nt][1] * tanhf_fast(0.5f * (x1f[nt][3] + c1));
                }
                ps0 += __shfl_xor_sync(0xffffffffu, ps0, 1);
                ps0 += __shfl_xor_sync(0xffffffffu, ps0, 2);
                ps1 += __shfl_xor_sync(0xffffffffu, ps1, 1);
                ps1 += __shfl_xor_sync(0xffffffffu, ps1, 2);
                if (qc == 0) {
                    sm[SM_PB + (k * 32 + sbw + g) * 4 + nh]     = ps0;
                    sm[SM_PB + (k * 32 + sbw + g + 8) * 4 + nh] = ps1;
                }
            }
        }

        // ---- convert + store next tile into other buffer ----
        if (have_next) {
            uint32_t* nxh = smu + SM_XB + (buf ^ 1) * BUFW;
            uint32_t* nxl = nxh + 2176;
            #pragma unroll
            for (int jj = 0; jj < 4; jj++) {
                float4 x = stg[jj];
                uint32_t h0 = pack_bf16x2(x.x, x.y);
                uint32_t h1 = pack_bf16x2(x.z, x.w);
                uint32_t l0 = pack_bf16x2(x.x - bf_lo(h0), x.y - bf_hi(h0));
                uint32_t l1 = pack_bf16x2(x.z - bf_lo(h1), x.w - bf_hi(h1));
                int p = srow * XP + (f4c * 4 + jj) * 2;
                *reinterpret_cast<uint2*>(nxh + p) = make_uint2(h0, h1);
                *reinterpret_cast<uint2*>(nxl + p) = make_uint2(l0, l1);
            }
        }
        __syncthreads();   // pb ready; next buffer fully stored

        // ---- read total p, mask, accumulate h ----
        const float4* pb4 = reinterpret_cast<const float4*>(sm + SM_PB);
        #pragma unroll
        for (int k = 0; k < K_LAB; k++) {
            const int tk = start + k;
            if (k < nk && s0 + sbw <= tk) {
                float4 p0 = pb4[k * 32 + sbw + g];
                float4 p1 = pb4[k * 32 + sbw + g + 8];
                float pt0 = (s0 + sbw + g     <= tk) ? (p0.x + p0.y + p0.z + p0.w) : 0.f;
                float pt1 = (s0 + sbw + g + 8 <= tk) ? (p1.x + p1.y + p1.z + p1.w) : 0.f;
                #pragma unroll
                for (int nt = 0; nt < 4; nt++) {
                    hacc[k][nt][0] += pt0 * x1f[nt][0] + pt1 * x1f[nt][2];
                    hacc[k][nt][1] += pt0 * x1f[nt][1] + pt1 * x1f[nt][3];
                }
            }
        }
        __syncthreads();   // pb reusable next tile
    }

    // ---- reduce hacc over row groups, stash per-mi partials (HB overlays XB) ----
    #pragma unroll
    for (int k = 0; k < K_LAB; k++)
        #pragma unroll
        for (int nt = 0; nt < 4; nt++)
            #pragma unroll
            for (int c = 0; c < 2; c++) {
                float v = hacc[k][nt][c];
                v += __shfl_xor_sync(0xffffffffu, v, 4);
                v += __shfl_xor_sync(0xffffffffu, v, 8);
                v += __shfl_xor_sync(0xffffffffu, v, 16);
                if (g == 0)
                    sm[SM_HB + (mi * 4 + k) * 128 + nh * 32 + nt * 8 + 2 * qc + c] = v;
            }
    __syncthreads();

    // ---- final output ----
    #pragma unroll
    for (int jj = 0; jj < 2; jj++) {
        int idx = tid + jj * THREADS;   // 0..511
        int k = idx >> 7, h = idx & 127;
        float v = 0.f;
        if (k < nk)
            v = sm[SM_HB + k * 128 + h] + sm[SM_HB + (4 + k) * 128 + h]
              + sm[SM_X2 + k * 128 + h];
        out[(size_t)b * (K_LAB * H_DIM) + idx] = v;
    }
}

extern "C" void kernel_launch(void* const* d_in, const int* in_sizes, int n_in,
                              void* d_out, int out_size)
{
    // input order: inputs, lengths, [label_len], w0, w1_w, w1_b, w2_w, w3_w
    const int base = (n_in >= 8) ? 3 : 2;
    const float* inputs  = (const float*)d_in[0];
    const int*   lengths = (const int*)d_in[1];
    const float* w0   = (const float*)d_in[base + 0];
    const float* w1_w = (const float*)d_in[base + 1];
    const float* w1_b = (const float*)d_in[base + 2];
    const float* w2_w = (const float*)d_in[base + 3];
    const float* w3_w = (const float*)d_in[base + 4];
    float* out = (float*)d_out;

    pack_kernel<<<16, 256>>>(w1_w);

    const size_t smem_bytes = (size_t)SM_TOT * sizeof(float);
    cudaFuncSetAttribute(fused_db_kernel,
                         cudaFuncAttributeMaxDynamicSharedMemorySize,
                         (int)smem_bytes);
    fused_db_kernel<<<GRID, THREADS, smem_bytes>>>(inputs, lengths, w0, w1_b,
                                                   w2_w, w3_w, out);
}

// round 5
// speedup vs baseline: 1.8522x; 1.0397x over previous
#include <cuda_runtime.h>
#include <cstdint>

#define T_DIM 200
#define B_DIM 2048
#define I_DIM 128
#define H_DIM 128
#define K_LAB 4
#define S_TILE 32
#define GRID   2048
#define THREADS 256
#define XP     68             // pair-row stride (u32 words): conflict-free A-frag reads
#define BI     (B_DIM * I_DIM)

// ---- shared memory layout (4-byte word offsets) ----
#define SM_WP   0                  // 16*8*32 uint4 = 16384 words (64 KB W pack)
#define SM_XB   16384              // per-group staging buffer: XH(2176)+XLO(2176)
#define BUFW    4352               // words per group buffer
#define SM_PB   (SM_XB + 2*BUFW)   // per-group p exchange: 2 * (4k*32row*4nh=512)
#define SM_CS   (SM_PB + 1024)     // 512
#define SM_X2   (SM_CS + 512)      // 512
#define SM_XL   (SM_X2 + 512)      // 512
#define SM_XM   (SM_XL + 512)      // 512
#define SM_PRE  (SM_XM + 512)      // 256
#define SM_HB   SM_XB              // reused after tile loop: 2grp*4k*128 = 1024
#define SM_TOT  (SM_PRE + 256)     // 28928 words = 115712 B? -> check: 16384+8704+1024+512*4+256 = 28416 words = 113664 B

// W1 packed as bf16 B fragments: [nt(16)][kc(8)][lane(32)] -> (bh0,bh1,bl0,bl1)
__device__ uint4 g_Wpack[16 * 8 * 32];

__device__ __forceinline__ uint32_t pack_bf16x2(float e_even, float e_odd) {
    uint32_t r;
    asm("cvt.rn.bf16x2.f32 %0, %1, %2;" : "=r"(r) : "f"(e_odd), "f"(e_even));
    return r;
}
__device__ __forceinline__ float bf_lo(uint32_t u) { return __uint_as_float(u << 16); }
__device__ __forceinline__ float bf_hi(uint32_t u) { return __uint_as_float(u & 0xffff0000u); }

__device__ __forceinline__ float tanhf_fast(float z) {
    float t;
    asm("tanh.approx.f32 %0, %1;" : "=f"(t) : "f"(z));
    return t;
}
__device__ __forceinline__ void mma_bf16(float* c,
                                         uint32_t a0, uint32_t a1, uint32_t a2, uint32_t a3,
                                         uint32_t b0, uint32_t b1) {
    asm volatile(
        "mma.sync.aligned.m16n8k16.row.col.f32.bf16.bf16.f32 "
        "{%0,%1,%2,%3}, {%4,%5,%6,%7}, {%8,%9}, {%0,%1,%2,%3};"
        : "+f"(c[0]), "+f"(c[1]), "+f"(c[2]), "+f"(c[3])
        : "r"(a0), "r"(a1), "r"(a2), "r"(a3), "r"(b0), "r"(b1));
}
__device__ __forceinline__ void barg(int id) {
    asm volatile("bar.sync %0, 128;" :: "r"(id) : "memory");
}

// ---------------- pack kernel: W1 -> bf16 hi/lo B-fragment layout ----------------
__global__ void pack_kernel(const float* __restrict__ w1_w) {
    int idx = blockIdx.x * blockDim.x + threadIdx.x;      // [nt(16)][kc(8)][lane(32)]
    if (idx >= 16 * 8 * 32) return;
    int lane = idx & 31;
    int kc   = (idx >> 5) & 7;
    int nt   = idx >> 8;
    int n  = nt * 8 + (lane >> 2);
    int k0 = kc * 16 + 2 * (lane & 3);
    const float* wr = w1_w + n * I_DIM;
    float w00 = wr[k0], w01 = wr[k0 + 1], w10 = wr[k0 + 8], w11 = wr[k0 + 9];
    uint32_t bh0 = pack_bf16x2(w00, w01);
    uint32_t bh1 = pack_bf16x2(w10, w11);
    float r00 = w00 - bf_lo(bh0), r01 = w01 - bf_hi(bh0);
    float r10 = w10 - bf_lo(bh1), r11 = w11 - bf_hi(bh1);
    uint4 v;
    v.x = bh0; v.y = bh1;
    v.z = pack_bf16x2(r00, r01);
    v.w = pack_bf16x2(r10, r11);
    g_Wpack[idx] = v;
}

// ---------------- main fused kernel ----------------
__global__ void __launch_bounds__(THREADS, 2)
fused_grp_kernel(const float* __restrict__ inputs,
                 const int*   __restrict__ lengths,
                 const float* __restrict__ w0,
                 const float* __restrict__ w1_b,
                 const float* __restrict__ w2_w,
                 const float* __restrict__ w3_w,
                 float* __restrict__ out)
{
    extern __shared__ float sm[];
    uint32_t* smu = reinterpret_cast<uint32_t*>(sm);

    const int tid   = threadIdx.x;
    const int lane  = tid & 31;
    const int wid   = tid >> 5;
    const int grp   = wid >> 2;      // group 0/1: alternating tiles
    const int nh    = wid & 3;       // h quarter (32 h = 4 n-tiles)
    const int g     = lane >> 2;     // row group 0..7
    const int qc    = lane & 3;      // col class 0..3
    const int local = tid & 127;     // index within group

    const int b     = blockIdx.x;
    const int len   = lengths[b];
    const int start = max(len - K_LAB, 0);
    const int nk    = min(len, K_LAB);

    // ---- copy packed W into smem ----
    uint4* wp4 = reinterpret_cast<uint4*>(smu + SM_WP);
    #pragma unroll
    for (int i = 0; i < 16; i++)
        wp4[tid + i * THREADS] = g_Wpack[tid + i * THREADS];

    // ---- hoist w0 (pre-halved) / bias fragments ----
    float w0h[4][2], b1r[4][2];
    float w0s = 0.f;
    #pragma unroll
    for (int nt = 0; nt < 4; nt++)
        #pragma unroll
        for (int c = 0; c < 2; c++) {
            int h = nh * 32 + nt * 8 + 2 * qc + c;
            w0h[nt][c] = 0.5f * w0[h];
            w0s += w0h[nt][c];
            b1r[nt][c] = w1_b[h];
        }

    // ---- prefix partial sums: i = tid&127, parity q = tid>>7, MLP-8 ----
    {
        const int i = tid & 127;
        const int q = tid >> 7;
        const float* ip = inputs + (size_t)b * I_DIM + i;
        float a0 = 0.f, a1 = 0.f, a2 = 0.f, a3 = 0.f;
        int s = q;
        for (; s + 16 <= start; s += 16) {
            float v0 = ip[(size_t)(s     ) * BI];
            float v1 = ip[(size_t)(s +  2) * BI];
            float v2 = ip[(size_t)(s +  4) * BI];
            float v3 = ip[(size_t)(s +  6) * BI];
            float v4 = ip[(size_t)(s +  8) * BI];
            float v5 = ip[(size_t)(s + 10) * BI];
            float v6 = ip[(size_t)(s + 12) * BI];
            float v7 = ip[(size_t)(s + 14) * BI];
            a0 += v0 + v4; a1 += v1 + v5; a2 += v2 + v6; a3 += v3 + v7;
        }
        for (; s < start; s += 2)
            a0 += ip[(size_t)s * BI];
        sm[SM_PRE + q * 128 + i] = (a0 + a1) + (a2 + a3);
    }
    __syncthreads();

    // ---- labeled snapshots (tid < 128) ----
    if (tid < 128) {
        const int i = tid;
        const float* ip = inputs + (size_t)b * I_DIM + i;
        float acc = sm[SM_PRE + i] + sm[SM_PRE + 128 + i];
        #pragma unroll
        for (int k = 0; k < K_LAB; k++) {
            float xv = 0.f, mv = 0.f;
            if (k < nk) {
                xv = ip[(size_t)(start + k) * BI];
                acc += xv;
                mv = acc / (float)(start + k + 1);
            }
            sm[SM_XL + k * 128 + i] = xv;
            sm[SM_XM + k * 128 + i] = mv;
        }
    }
    __syncthreads();

    // ---- c[k][h] = x2_lab + w3 @ m  (h = tid&127, k in {kq, kq+2}) ----
    {
        const int h  = tid & 127;
        const int kq = tid >> 7;
        float x2a = 0.f, x2b = 0.f, wma = 0.f, wmb = 0.f;
        const float4* w2r = reinterpret_cast<const float4*>(w2_w + h * I_DIM);
        const float4* w3r = reinterpret_cast<const float4*>(w3_w + h * I_DIM);
        #pragma unroll 4
        for (int i4 = 0; i4 < 32; i4++) {
            float4 a2 = w2r[i4];
            float4 a3 = w3r[i4];
            float4 xa = *reinterpret_cast<const float4*>(&sm[SM_XL + kq * 128 + i4 * 4]);
            float4 xb = *reinterpret_cast<const float4*>(&sm[SM_XL + (kq + 2) * 128 + i4 * 4]);
            float4 ma = *reinterpret_cast<const float4*>(&sm[SM_XM + kq * 128 + i4 * 4]);
            float4 mb = *reinterpret_cast<const float4*>(&sm[SM_XM + (kq + 2) * 128 + i4 * 4]);
            x2a += a2.x * xa.x + a2.y * xa.y + a2.z * xa.z + a2.w * xa.w;
            x2b += a2.x * xb.x + a2.y * xb.y + a2.z * xb.z + a2.w * xb.w;
            wma += a3.x * ma.x + a3.y * ma.y + a3.z * ma.z + a3.w * ma.w;
            wmb += a3.x * mb.x + a3.y * mb.y + a3.z * mb.z + a3.w * mb.w;
        }
        sm[SM_CS + kq * 128 + h]       = x2a + wma;
        sm[SM_CS + (kq + 2) * 128 + h] = x2b + wmb;
        sm[SM_X2 + kq * 128 + h]       = x2a;
        sm[SM_X2 + (kq + 2) * 128 + h] = x2b;
    }
    __syncthreads();

    float hacc[K_LAB][4][2];
    #pragma unroll
    for (int k = 0; k < K_LAB; k++)
        #pragma unroll
        for (int nt = 0; nt < 4; nt++) { hacc[k][nt][0] = 0.f; hacc[k][nt][1] = 0.f; }

    const int n_tiles = (len + S_TILE - 1) >> 5;
    uint32_t* xh = smu + SM_XB + grp * BUFW;
    uint32_t* xl = xh + 2176;
    float*    pbg = sm + SM_PB + grp * 512;
    const int bar = 1 + grp;

    const int srow = local >> 2;     // staging row 0..31 (4 threads/row)
    const int f4c  = local & 3;

    // ================= group tile loop (t = grp, grp+2, ...) =================
    for (int t = grp; t < n_tiles; t += 2) {
        const int s0 = t * S_TILE;

        // ---- stage: coalesced LDG + convert + STS into group buffer ----
        {
            const int gs = s0 + srow;
            const bool vld = (gs < len);
            const float4* src = reinterpret_cast<const float4*>(
                inputs + (size_t)gs * BI + (size_t)b * I_DIM);
            #pragma unroll
            for (int j = 0; j < 8; j++) {
                const int c4 = j * 4 + f4c;          // float4 index in row: coalesced per j
                float4 x = vld ? src[c4] : make_float4(0.f, 0.f, 0.f, 0.f);
                uint32_t h0 = pack_bf16x2(x.x, x.y);
                uint32_t h1 = pack_bf16x2(x.z, x.w);
                uint32_t l0 = pack_bf16x2(x.x - bf_lo(h0), x.y - bf_hi(h0));
                uint32_t l1 = pack_bf16x2(x.z - bf_lo(h1), x.w - bf_hi(h1));
                int p = srow * XP + c4 * 2;
                *reinterpret_cast<uint2*>(xh + p) = make_uint2(h0, h1);
                *reinterpret_cast<uint2*>(xl + p) = make_uint2(l0, l1);
            }
        }
        barg(bar);

        // ---- 3-term bf16 MMA: warp tile 32s x 32h ----
        float x1f[2][4][4];
        #pragma unroll
        for (int mt = 0; mt < 2; mt++)
            #pragma unroll
            for (int nt = 0; nt < 4; nt++)
                #pragma unroll
                for (int r = 0; r < 4; r++) x1f[mt][nt][r] = 0.f;

        #pragma unroll
        for (int kc = 0; kc < 8; kc++) {
            uint32_t ah[2][4], al[2][4];
            #pragma unroll
            for (int mt = 0; mt < 2; mt++) {
                const int rb = (mt * 16 + g) * XP + kc * 8 + qc;
                ah[mt][0] = xh[rb];
                ah[mt][1] = xh[rb + 8 * XP];
                ah[mt][2] = xh[rb + 4];
                ah[mt][3] = xh[rb + 8 * XP + 4];
                al[mt][0] = xl[rb];
                al[mt][1] = xl[rb + 8 * XP];
                al[mt][2] = xl[rb + 4];
                al[mt][3] = xl[rb + 8 * XP + 4];
            }
            #pragma unroll
            for (int nt = 0; nt < 4; nt++) {
                uint4 bq = wp4[((nh * 4 + nt) * 8 + kc) * 32 + lane];
                #pragma unroll
                for (int mt = 0; mt < 2; mt++) {
                    mma_bf16(x1f[mt][nt], ah[mt][0], ah[mt][1], ah[mt][2], ah[mt][3], bq.x, bq.y);
                    mma_bf16(x1f[mt][nt], al[mt][0], al[mt][1], al[mt][2], al[mt][3], bq.x, bq.y);
                    mma_bf16(x1f[mt][nt], ah[mt][0], ah[mt][1], ah[mt][2], ah[mt][3], bq.z, bq.w);
                }
            }
        }
        #pragma unroll
        for (int mt = 0; mt < 2; mt++)
            #pragma unroll
            for (int nt = 0; nt < 4; nt++) {
                x1f[mt][nt][0] += b1r[nt][0];
                x1f[mt][nt][1] += b1r[nt][1];
                x1f[mt][nt][2] += b1r[nt][0];
                x1f[mt][nt][3] += b1r[nt][1];
            }

        // ---- sigmoid (tanh form) + w0 partial sums ----
        #pragma unroll
        for (int k = 0; k < K_LAB; k++) {
            const int tk = start + k;
            if (k < nk && s0 <= tk) {
                float ps[2][2];
                #pragma unroll
                for (int mt = 0; mt < 2; mt++) {
                    ps[mt][0] = w0s; ps[mt][1] = w0s;
                    #pragma unroll
                    for (int nt = 0; nt < 4; nt++) {
                        float c0 = sm[SM_CS + k * 128 + nh * 32 + nt * 8 + 2 * qc];
                        float c1 = sm[SM_CS + k * 128 + nh * 32 + nt * 8 + 2 * qc + 1];
                        ps[mt][0] += w0h[nt][0] * tanhf_fast(0.5f * (x1f[mt][nt][0] + c0))
                                   + w0h[nt][1] * tanhf_fast(0.5f * (x1f[mt][nt][1] + c1));
                        ps[mt][1] += w0h[nt][0] * tanhf_fast(0.5f * (x1f[mt][nt][2] + c0))
                                   + w0h[nt][1] * tanhf_fast(0.5f * (x1f[mt][nt][3] + c1));
                    }
                }
                #pragma unroll
                for (int mt = 0; mt < 2; mt++)
                    #pragma unroll
                    for (int r = 0; r < 2; r++) {
                        float v = ps[mt][r];
                        v += __shfl_xor_sync(0xffffffffu, v, 1);
                        v += __shfl_xor_sync(0xffffffffu, v, 2);
                        ps[mt][r] = v;
                    }
                if (qc == 0) {
                    #pragma unroll
                    for (int mt = 0; mt < 2; mt++) {
                        pbg[(k * 32 + mt * 16 + g) * 4 + nh]     = ps[mt][0];
                        pbg[(k * 32 + mt * 16 + g + 8) * 4 + nh] = ps[mt][1];
                    }
                }
            }
        }
        barg(bar);

        // ---- read total p, mask, accumulate h ----
        const float4* pb4 = reinterpret_cast<const float4*>(pbg);
        #pragma unroll
        for (int k = 0; k < K_LAB; k++) {
            const int tk = start + k;
            if (k < nk && s0 <= tk) {
                #pragma unroll
                for (int mt = 0; mt < 2; mt++) {
                    const int r0 = mt * 16 + g;
                    float4 p0 = pb4[k * 32 + r0];
                    float4 p1 = pb4[k * 32 + r0 + 8];
                    float pt0 = (s0 + r0     <= tk) ? (p0.x + p0.y + p0.z + p0.w) : 0.f;
                    float pt1 = (s0 + r0 + 8 <= tk) ? (p1.x + p1.y + p1.z + p1.w) : 0.f;
                    #pragma unroll
                    for (int nt = 0; nt < 4; nt++) {
                        hacc[k][nt][0] += pt0 * x1f[mt][nt][0] + pt1 * x1f[mt][nt][2];
                        hacc[k][nt][1] += pt0 * x1f[mt][nt][1] + pt1 * x1f[mt][nt][3];
                    }
                }
            }
        }
        // next PB write happens only after next barg(bar) -> safe without a barrier here
    }

    // ---- reduce hacc over row groups, stash per-group partials (HB overlays XB) ----
    __syncthreads();   // both groups done with buffers
    #pragma unroll
    for (int k = 0; k < K_LAB; k++)
        #pragma unroll
        for (int nt = 0; nt < 4; nt++)
            #pragma unroll
            for (int c = 0; c < 2; c++) {
                float v = hacc[k][nt][c];
                v += __shfl_xor_sync(0xffffffffu, v, 4);
                v += __shfl_xor_sync(0xffffffffu, v, 8);
                v += __shfl_xor_sync(0xffffffffu, v, 16);
                if (g == 0)
                    sm[SM_HB + (grp * 4 + k) * 128 + nh * 32 + nt * 8 + 2 * qc + c] = v;
            }
    __syncthreads();

    // ---- final output ----
    #pragma unroll
    for (int jj = 0; jj < 2; jj++) {
        int idx = tid + jj * THREADS;   // 0..511
        int k = idx >> 7, h = idx & 127;
        float v = 0.f;
        if (k < nk)
            v = sm[SM_HB + k * 128 + h] + sm[SM_HB + (4 + k) * 128 + h]
              + sm[SM_X2 + k * 128 + h];
        out[(size_t)b * (K_LAB * H_DIM) + idx] = v;
    }
}

extern "C" void kernel_launch(void* const* d_in, const int* in_sizes, int n_in,
                              void* d_out, int out_size)
{
    // input order: inputs, lengths, [label_len], w0, w1_w, w1_b, w2_w, w3_w
    const int base = (n_in >= 8) ? 3 : 2;
    const float* inputs  = (const float*)d_in[0];
    const int*   lengths = (const int*)d_in[1];
    const float* w0   = (const float*)d_in[base + 0];
    const float* w1_w = (const float*)d_in[base + 1];
    const float* w1_b = (const float*)d_in[base + 2];
    const float* w2_w = (const float*)d_in[base + 3];
    const float* w3_w = (const float*)d_in[base + 4];
    float* out = (float*)d_out;

    pack_kernel<<<16, 256>>>(w1_w);

    const size_t smem_bytes = (size_t)SM_TOT * sizeof(float);
    cudaFuncSetAttribute(fused_grp_kernel,
                         cudaFuncAttributeMaxDynamicSharedMemorySize,
                         (int)smem_bytes);
    fused_grp_kernel<<<GRID, THREADS, smem_bytes>>>(inputs, lengths, w0, w1_b,
                                                    w2_w, w3_w, out);
}

// round 7
// speedup vs baseline: 3.1875x; 1.7209x over previous
#include <cuda_runtime.h>
#include <cstdint>

#define T_DIM 200
#define B_DIM 2048
#define I_DIM 128
#define H_DIM 128
#define K_LAB 4
#define S_TILE 32
#define GRID   2048
#define THREADS 256
#define XP     68             // pair-row stride (u32 words): conflict-free A-frag reads
#define BI     (B_DIM * I_DIM)

// ---- shared memory layout (4-byte word offsets) ----
#define SM_WP   0                  // 16*8*32 uint4 = 16384 words (64 KB W1 pack)
#define SM_XB   16384              // per-group staging buffer: XH(2176)+XLO(2176)
#define BUFW    4352               // words per group buffer
#define SM_PB   (SM_XB + 2*BUFW)   // per-group p exchange: 2 * 512
#define SM_CS   (SM_PB + 1024)     // 512
#define SM_X2   (SM_CS + 512)      // 512
#define SM_XL   (SM_X2 + 512)      // 512
#define SM_XM   (SM_XL + 512)      // 512
#define SM_PRE  (SM_XM + 512)      // 256
#define SM_HB   SM_XB              // reused after tile loop: 2grp*4k*128 = 1024
#define SM_TOT  (SM_PRE + 256)     // 28416 words = 113664 B

#define W1_FRAGS  (16 * 8 * 32)    // 4096
#define W23_FRAGS (2 * 16 * 8 * 32)

// W1 packed as bf16 B fragments: [nt(16)][kc(8)][lane(32)] -> (bh0,bh1,bl0,bl1)
__device__ uint4 g_Wpack[W1_FRAGS];
// W2 (pass 0) and W3 (pass 1) packed the same way: [p(2)][nt(16)][kc(8)][lane(32)]
__device__ uint4 g_W23pack[W23_FRAGS];

__device__ __forceinline__ uint32_t pack_bf16x2(float e_even, float e_odd) {
    uint32_t r;
    asm("cvt.rn.bf16x2.f32 %0, %1, %2;" : "=r"(r) : "f"(e_odd), "f"(e_even));
    return r;
}
__device__ __forceinline__ float bf_lo(uint32_t u) { return __uint_as_float(u << 16); }
__device__ __forceinline__ float bf_hi(uint32_t u) { return __uint_as_float(u & 0xffff0000u); }

__device__ __forceinline__ float tanhf_fast(float z) {
    float t;
    asm("tanh.approx.f32 %0, %1;" : "=f"(t) : "f"(z));
    return t;
}
__device__ __forceinline__ void mma_bf16(float* c,
                                         uint32_t a0, uint32_t a1, uint32_t a2, uint32_t a3,
                                         uint32_t b0, uint32_t b1) {
    asm volatile(
        "mma.sync.aligned.m16n8k16.row.col.f32.bf16.bf16.f32 "
        "{%0,%1,%2,%3}, {%4,%5,%6,%7}, {%8,%9}, {%0,%1,%2,%3};"
        : "+f"(c[0]), "+f"(c[1]), "+f"(c[2]), "+f"(c[3])
        : "r"(a0), "r"(a1), "r"(a2), "r"(a3), "r"(b0), "r"(b1));
}
__device__ __forceinline__ void ldsm4(uint32_t& r0, uint32_t& r1, uint32_t& r2,
                                      uint32_t& r3, uint32_t a) {
    asm volatile("ldmatrix.sync.aligned.m8n8.x4.shared.b16 {%0,%1,%2,%3}, [%4];"
                 : "=r"(r0), "=r"(r1), "=r"(r2), "=r"(r3) : "r"(a));
}
__device__ __forceinline__ void barg(int id) {
    asm volatile("bar.sync %0, 128;" :: "r"(id) : "memory");
}

// ---------------- pack kernel: W1/W2/W3 -> bf16 hi/lo B-fragment layouts ----------------
__global__ void pack_kernel(const float* __restrict__ w1_w,
                            const float* __restrict__ w2_w,
                            const float* __restrict__ w3_w) {
    int idx = blockIdx.x * blockDim.x + threadIdx.x;   // 0 .. W1_FRAGS + W23_FRAGS - 1
    if (idx >= W1_FRAGS + W23_FRAGS) return;

    const float* src;
    uint4* dst;
    int nt, kc, lane;
    if (idx < W1_FRAGS) {             // W1: [nt(16)][kc(8)][lane(32)]
        lane = idx & 31; kc = (idx >> 5) & 7; nt = (idx >> 8) & 15;
        src = w1_w; dst = g_Wpack + idx;
    } else {                          // W2/W3: [p(2)][nt(16)][kc(8)][lane(32)]
        int i2 = idx - W1_FRAGS;
        lane = i2 & 31; kc = (i2 >> 5) & 7; nt = (i2 >> 8) & 15;
        int p = i2 >> 12;
        src = p ? w3_w : w2_w;
        dst = g_W23pack + i2;
    }
    int n  = nt * 8 + (lane >> 2);
    int k0 = kc * 16 + 2 * (lane & 3);
    const float* wr = src + n * I_DIM;
    float w00 = wr[k0], w01 = wr[k0 + 1], w10 = wr[k0 + 8], w11 = wr[k0 + 9];
    uint32_t bh0 = pack_bf16x2(w00, w01);
    uint32_t bh1 = pack_bf16x2(w10, w11);
    uint4 v;
    v.x = bh0; v.y = bh1;
    v.z = pack_bf16x2(w00 - bf_lo(bh0), w01 - bf_hi(bh0));
    v.w = pack_bf16x2(w10 - bf_lo(bh1), w11 - bf_hi(bh1));
    *dst = v;
}

// ---------------- main fused kernel ----------------
__global__ void __launch_bounds__(THREADS, 2)
fused_r7_kernel(const float* __restrict__ inputs,
                const int*   __restrict__ lengths,
                const float* __restrict__ w0,
                const float* __restrict__ w1_b,
                float* __restrict__ out)
{
    extern __shared__ float sm[];
    uint32_t* smu = reinterpret_cast<uint32_t*>(sm);

    const int tid   = threadIdx.x;
    const int lane  = tid & 31;
    const int wid   = tid >> 5;
    const int grp   = wid >> 2;      // group 0/1: alternating tiles
    const int nh    = wid & 3;       // h quarter (32 h = 4 n-tiles)
    const int g     = lane >> 2;     // row group 0..7
    const int qc    = lane & 3;      // col class 0..3
    const int local = tid & 127;     // index within group

    const int b     = blockIdx.x;
    const int len   = lengths[b];
    const int start = max(len - K_LAB, 0);
    const int nk    = min(len, K_LAB);

    // ---- copy packed W1 into smem ----
    uint4* wp4 = reinterpret_cast<uint4*>(smu + SM_WP);
    #pragma unroll
    for (int i = 0; i < 16; i++)
        wp4[tid + i * THREADS] = g_Wpack[tid + i * THREADS];

    // ---- hoist w0 (pre-halved) / bias fragments ----
    float w0h[4][2], b1r[4][2];
    float w0s = 0.f;
    #pragma unroll
    for (int nt = 0; nt < 4; nt++)
        #pragma unroll
        for (int c = 0; c < 2; c++) {
            int h = nh * 32 + nt * 8 + 2 * qc + c;
            w0h[nt][c] = 0.5f * w0[h];
            w0s += w0h[nt][c];
            b1r[nt][c] = w1_b[h];
        }

    // ldmatrix lane address pattern (word offset within a buffer)
    const uint32_t arow = (uint32_t)((lane & 15) * XP + (lane >> 4) * 4);

    // ---- prefix partial sums: i = tid&127, parity q = tid>>7, MLP-8 ----
    {
        const int i = tid & 127;
        const int q = tid >> 7;
        const float* ip = inputs + (size_t)b * I_DIM + i;
        float a0 = 0.f, a1 = 0.f, a2 = 0.f, a3 = 0.f;
        int s = q;
        for (; s + 16 <= start; s += 16) {
            float v0 = ip[(size_t)(s     ) * BI];
            float v1 = ip[(size_t)(s +  2) * BI];
            float v2 = ip[(size_t)(s +  4) * BI];
            float v3 = ip[(size_t)(s +  6) * BI];
            float v4 = ip[(size_t)(s +  8) * BI];
            float v5 = ip[(size_t)(s + 10) * BI];
            float v6 = ip[(size_t)(s + 12) * BI];
            float v7 = ip[(size_t)(s + 14) * BI];
            a0 += v0 + v4; a1 += v1 + v5; a2 += v2 + v6; a3 += v3 + v7;
        }
        for (; s < start; s += 2)
            a0 += ip[(size_t)s * BI];
        sm[SM_PRE + q * 128 + i] = (a0 + a1) + (a2 + a3);
    }
    __syncthreads();

    // ---- labeled snapshots (tid < 128) ----
    if (tid < 128) {
        const int i = tid;
        const float* ip = inputs + (size_t)b * I_DIM + i;
        float acc = sm[SM_PRE + i] + sm[SM_PRE + 128 + i];
        #pragma unroll
        for (int k = 0; k < K_LAB; k++) {
            float xv = 0.f, mv = 0.f;
            if (k < nk) {
                xv = ip[(size_t)(start + k) * BI];
                acc += xv;
                mv = acc / (float)(start + k + 1);
            }
            sm[SM_XL + k * 128 + i] = xv;
            sm[SM_XM + k * 128 + i] = mv;
        }
    }
    __syncthreads();

    // ---- build c-phase A tile in XB buffer 0: rows 0-3 = xlab, 4-7 = xm, 8-15 = 0 ----
    {
        uint32_t* xh = smu + SM_XB;
        uint32_t* xl = xh + 2176;
        const int r   = tid >> 5;           // 0..7
        const int t32 = tid & 31;
        const float4 v = *reinterpret_cast<const float4*>(
            &sm[(r < 4 ? SM_XL + r * 128 : SM_XM + (r - 4) * 128) + t32 * 4]);
        uint32_t h0 = pack_bf16x2(v.x, v.y);
        uint32_t h1 = pack_bf16x2(v.z, v.w);
        uint32_t l0 = pack_bf16x2(v.x - bf_lo(h0), v.y - bf_hi(h0));
        uint32_t l1 = pack_bf16x2(v.z - bf_lo(h1), v.w - bf_hi(h1));
        int p = r * XP + t32 * 2;
        *reinterpret_cast<uint2*>(xh + p) = make_uint2(h0, h1);
        *reinterpret_cast<uint2*>(xl + p) = make_uint2(l0, l1);
        int z = (8 + r) * XP + t32 * 2;
        *reinterpret_cast<uint2*>(xh + z) = make_uint2(0u, 0u);
        *reinterpret_cast<uint2*>(xl + z) = make_uint2(0u, 0u);
    }
    __syncthreads();

    // ---- c[k][h] via MMA: pass0 B=W2 (-> x2), pass1 B=W3 (rows 4-7 -> wms) ----
    {
        const uint32_t ca_h = (uint32_t)__cvta_generic_to_shared(smu + SM_XB + arow);
        const uint32_t ca_l = ca_h + 2176 * 4;

        float acc1[2][4], acc2[2][4];
        #pragma unroll
        for (int j = 0; j < 2; j++)
            #pragma unroll
            for (int r = 0; r < 4; r++) { acc1[j][r] = 0.f; acc2[j][r] = 0.f; }

        #pragma unroll
        for (int p = 0; p < 2; p++) {
            float (*acc)[4] = p ? acc2 : acc1;
            #pragma unroll
            for (int kc = 0; kc < 8; kc++) {
                uint32_t ah0, ah1, ah2, ah3, al0, al1, al2, al3;
                ldsm4(ah0, ah1, ah2, ah3, ca_h + kc * 32);
                ldsm4(al0, al1, al2, al3, ca_l + kc * 32);
                #pragma unroll
                for (int j = 0; j < 2; j++) {
                    const int ntg = 2 * wid + j;
                    uint4 bq = g_W23pack[((p * 16 + ntg) * 8 + kc) * 32 + lane];
                    mma_bf16(acc[j], ah0, ah1, ah2, ah3, bq.x, bq.y);
                    mma_bf16(acc[j], al0, al1, al2, al3, bq.x, bq.y);
                    mma_bf16(acc[j], ah0, ah1, ah2, ah3, bq.z, bq.w);
                }
            }
        }
        // extract: k = g (g<4), x2 = acc1 row g, wms = acc2 row g+4 (lane+16)
        #pragma unroll
        for (int j = 0; j < 2; j++)
            #pragma unroll
            for (int c2 = 0; c2 < 2; c2++) {
                float wmsv = __shfl_down_sync(0xffffffffu, acc2[j][c2], 16);
                if (g < 4) {
                    int h = (2 * wid + j) * 8 + 2 * qc + c2;
                    sm[SM_X2 + g * 128 + h] = acc1[j][c2];
                    sm[SM_CS + g * 128 + h] = acc1[j][c2] + wmsv;
                }
            }
    }
    __syncthreads();

    float hacc[K_LAB][4][2];
    #pragma unroll
    for (int k = 0; k < K_LAB; k++)
        #pragma unroll
        for (int nt = 0; nt < 4; nt++) { hacc[k][nt][0] = 0.f; hacc[k][nt][1] = 0.f; }

    const int n_tiles = (len + S_TILE - 1) >> 5;
    uint32_t* xh = smu + SM_XB + grp * BUFW;
    uint32_t* xl = xh + 2176;
    float*    pbg = sm + SM_PB + grp * 512;
    const int bar = 1 + grp;

    const uint32_t sa_h = (uint32_t)__cvta_generic_to_shared(xh + arow);
    const uint32_t sa_l = sa_h + 2176 * 4;

    const int srow = local >> 2;     // staging row 0..31 (4 threads/row)
    const int f4c  = local & 3;

    // ================= group tile loop (t = grp, grp+2, ...) =================
    for (int t = grp; t < n_tiles; t += 2) {
        const int s0 = t * S_TILE;

        // ---- stage: coalesced LDG + convert + STS into group buffer ----
        {
            const int gs = s0 + srow;
            const bool vld = (gs < len);
            const float4* src = reinterpret_cast<const float4*>(
                inputs + (size_t)gs * BI + (size_t)b * I_DIM);
            #pragma unroll
            for (int j = 0; j < 8; j++) {
                const int c4 = j * 4 + f4c;          // coalesced per j
                float4 x = vld ? src[c4] : make_float4(0.f, 0.f, 0.f, 0.f);
                uint32_t h0 = pack_bf16x2(x.x, x.y);
                uint32_t h1 = pack_bf16x2(x.z, x.w);
                uint32_t l0 = pack_bf16x2(x.x - bf_lo(h0), x.y - bf_hi(h0));
                uint32_t l1 = pack_bf16x2(x.z - bf_lo(h1), x.w - bf_hi(h1));
                int p = srow * XP + c4 * 2;
                *reinterpret_cast<uint2*>(xh + p) = make_uint2(h0, h1);
                *reinterpret_cast<uint2*>(xl + p) = make_uint2(l0, l1);
            }
        }
        barg(bar);

        // ---- 3-term bf16 MMA: warp tile 32s x 32h, A-frags via ldmatrix ----
        float x1f[2][4][4];
        #pragma unroll
        for (int mt = 0; mt < 2; mt++)
            #pragma unroll
            for (int nt = 0; nt < 4; nt++)
                #pragma unroll
                for (int r = 0; r < 4; r++) x1f[mt][nt][r] = 0.f;

        #pragma unroll
        for (int kc = 0; kc < 8; kc++) {
            uint32_t ah[2][4], al[2][4];
            #pragma unroll
            for (int mt = 0; mt < 2; mt++) {
                const uint32_t off = (uint32_t)(mt * 16 * XP * 4 + kc * 32);
                ldsm4(ah[mt][0], ah[mt][1], ah[mt][2], ah[mt][3], sa_h + off);
                ldsm4(al[mt][0], al[mt][1], al[mt][2], al[mt][3], sa_l + off);
            }
            #pragma unroll
            for (int nt = 0; nt < 4; nt++) {
                uint4 bq = wp4[((nh * 4 + nt) * 8 + kc) * 32 + lane];
                #pragma unroll
                for (int mt = 0; mt < 2; mt++) {
                    mma_bf16(x1f[mt][nt], ah[mt][0], ah[mt][1], ah[mt][2], ah[mt][3], bq.x, bq.y);
                    mma_bf16(x1f[mt][nt], al[mt][0], al[mt][1], al[mt][2], al[mt][3], bq.x, bq.y);
                    mma_bf16(x1f[mt][nt], ah[mt][0], ah[mt][1], ah[mt][2], ah[mt][3], bq.z, bq.w);
                }
            }
        }
        #pragma unroll
        for (int mt = 0; mt < 2; mt++)
            #pragma unroll
            for (int nt = 0; nt < 4; nt++) {
                x1f[mt][nt][0] += b1r[nt][0];
                x1f[mt][nt][1] += b1r[nt][1];
                x1f[mt][nt][2] += b1r[nt][0];
                x1f[mt][nt][3] += b1r[nt][1];
            }

        // ---- sigmoid (tanh form) + w0 partial sums ----
        #pragma unroll
        for (int k = 0; k < K_LAB; k++) {
            const int tk = start + k;
            if (k < nk && s0 <= tk) {
                float ps[2][2];
                ps[0][0] = w0s; ps[0][1] = w0s; ps[1][0] = w0s; ps[1][1] = w0s;
                #pragma unroll
                for (int nt = 0; nt < 4; nt++) {
                    float2 cv = *reinterpret_cast<const float2*>(
                        &sm[SM_CS + k * 128 + nh * 32 + nt * 8 + 2 * qc]);
                    #pragma unroll
                    for (int mt = 0; mt < 2; mt++) {
                        ps[mt][0] += w0h[nt][0] * tanhf_fast(0.5f * (x1f[mt][nt][0] + cv.x))
                                   + w0h[nt][1] * tanhf_fast(0.5f * (x1f[mt][nt][1] + cv.y));
                        ps[mt][1] += w0h[nt][0] * tanhf_fast(0.5f * (x1f[mt][nt][2] + cv.x))
                                   + w0h[nt][1] * tanhf_fast(0.5f * (x1f[mt][nt][3] + cv.y));
                    }
                }
                #pragma unroll
                for (int mt = 0; mt < 2; mt++)
                    #pragma unroll
                    for (int r = 0; r < 2; r++) {
                        float v = ps[mt][r];
                        v += __shfl_xor_sync(0xffffffffu, v, 1);
                        v += __shfl_xor_sync(0xffffffffu, v, 2);
                        ps[mt][r] = v;
                    }
                if (qc == 0) {
                    #pragma unroll
                    for (int mt = 0; mt < 2; mt++) {
                        pbg[(k * 32 + mt * 16 + g) * 4 + nh]     = ps[mt][0];
                        pbg[(k * 32 + mt * 16 + g + 8) * 4 + nh] = ps[mt][1];
                    }
                }
            }
        }
        barg(bar);

        // ---- read total p, mask, accumulate h ----
        const float4* pb4 = reinterpret_cast<const float4*>(pbg);
        #pragma unroll
        for (int k = 0; k < K_LAB; k++) {
            const int tk = start + k;
            if (k < nk && s0 <= tk) {
                #pragma unroll
                for (int mt = 0; mt < 2; mt++) {
                    const int r0 = mt * 16 + g;
                    float4 p0 = pb4[k * 32 + r0];
                    float4 p1 = pb4[k * 32 + r0 + 8];
                    float pt0 = (s0 + r0     <= tk) ? (p0.x + p0.y + p0.z + p0.w) : 0.f;
                    float pt1 = (s0 + r0 + 8 <= tk) ? (p1.x + p1.y + p1.z + p1.w) : 0.f;
                    #pragma unroll
                    for (int nt = 0; nt < 4; nt++) {
                        hacc[k][nt][0] += pt0 * x1f[mt][nt][0] + pt1 * x1f[mt][nt][2];
                        hacc[k][nt][1] += pt0 * x1f[mt][nt][1] + pt1 * x1f[mt][nt][3];
                    }
                }
            }
        }
        // next PB write only happens after the next barg(bar) -> safe
    }

    // ---- reduce hacc over row groups, stash per-group partials (HB overlays XB) ----
    __syncthreads();   // both groups done with buffers
    #pragma unroll
    for (int k = 0; k < K_LAB; k++)
        #pragma unroll
        for (int nt = 0; nt < 4; nt++)
            #pragma unroll
            for (int c = 0; c < 2; c++) {
                float v = hacc[k][nt][c];
                v += __shfl_xor_sync(0xffffffffu, v, 4);
                v += __shfl_xor_sync(0xffffffffu, v, 8);
                v += __shfl_xor_sync(0xffffffffu, v, 16);
                if (g == 0)
                    sm[SM_HB + (grp * 4 + k) * 128 + nh * 32 + nt * 8 + 2 * qc + c] = v;
            }
    __syncthreads();

    // ---- final output ----
    #pragma unroll
    for (int jj = 0; jj < 2; jj++) {
        int idx = tid + jj * THREADS;   // 0..511
        int k = idx >> 7, h = idx & 127;
        float v = 0.f;
        if (k < nk)
            v = sm[SM_HB + k * 128 + h] + sm[SM_HB + (4 + k) * 128 + h]
              + sm[SM_X2 + k * 128 + h];
        out[(size_t)b * (K_LAB * H_DIM) + idx] = v;
    }
}

extern "C" void kernel_launch(void* const* d_in, const int* in_sizes, int n_in,
                              void* d_out, int out_size)
{
    // input order: inputs, lengths, [label_len], w0, w1_w, w1_b, w2_w, w3_w
    const int base = (n_in >= 8) ? 3 : 2;
    const float* inputs  = (const float*)d_in[0];
    const int*   lengths = (const int*)d_in[1];
    const float* w0   = (const float*)d_in[base + 0];
    const float* w1_w = (const float*)d_in[base + 1];
    const float* w1_b = (const float*)d_in[base + 2];
    const float* w2_w = (const float*)d_in[base + 3];
    const float* w3_w = (const float*)d_in[base + 4];
    float* out = (float*)d_out;

    pack_kernel<<<48, 256>>>(w1_w, w2_w, w3_w);   // 12288 threads

    const size_t smem_bytes = (size_t)SM_TOT * sizeof(float);
    cudaFuncSetAttribute(fused_r7_kernel,
                         cudaFuncAttributeMaxDynamicSharedMemorySize,
                         (int)smem_bytes);
    fused_r7_kernel<<<GRID, THREADS, smem_bytes>>>(inputs, lengths, w0, w1_b, out);
}

// round 8
// speedup vs baseline: 3.8504x; 1.2079x over previous
#include <cuda_runtime.h>
#include <cuda_fp16.h>
#include <cstdint>

#define T_DIM 200
#define B_DIM 2048
#define I_DIM 128
#define H_DIM 128
#define K_LAB 4
#define S_TILE 32
#define GRID   2048
#define THREADS 256
#define XP     68             // pair-row stride (u32 words): conflict-free A-frag reads
#define BI     (B_DIM * I_DIM)

// ---- shared memory layout (4-byte word offsets) ----
#define SM_WP   0                  // 16*8*32 uint2 = 8192 words (32 KB W1 pack, fp16)
#define SM_XB   8192               // per-group staging buffer: XH(2176)+XLO(2176)
#define BUFW    4352               // words per group buffer
#define SM_PB   (SM_XB + 2*BUFW)   // per-group p exchange: 2 * 512
#define SM_CS   (SM_PB + 1024)     // 512
#define SM_X2   (SM_CS + 512)      // 512
#define SM_XL   (SM_X2 + 512)      // 512
#define SM_XM   (SM_XL + 512)      // 512
#define SM_PRE  (SM_XM + 512)      // 256
#define SM_HB   SM_XB              // reused after tile loop: 2grp*4k*128 = 1024
#define SM_TOT  (SM_PRE + 256)     // 20224 words = 80896 B

#define W1_FRAGS  (16 * 8 * 32)    // 4096
#define W23_FRAGS (2 * 16 * 8 * 32)

// W1 packed as fp16 B fragments: [nt(16)][kc(8)][lane(32)] -> (wh0, wh1)
__device__ uint2 g_Wpack[W1_FRAGS];
// W2 (pass 0) and W3 (pass 1) packed the same way: [p(2)][nt(16)][kc(8)][lane(32)]
__device__ uint2 g_W23pack[W23_FRAGS];

__device__ __forceinline__ uint32_t pack_f16x2(float e_even, float e_odd) {
    uint32_t r;
    asm("cvt.rn.f16x2.f32 %0, %1, %2;" : "=r"(r) : "f"(e_odd), "f"(e_even));
    return r;
}
__device__ __forceinline__ float2 unpack_f16x2(uint32_t u) {
    __half2 h = *reinterpret_cast<__half2*>(&u);
    return __half22float2(h);
}

__device__ __forceinline__ float tanhf_fast(float z) {
    float t;
    asm("tanh.approx.f32 %0, %1;" : "=f"(t) : "f"(z));
    return t;
}
__device__ __forceinline__ void mma_f16(float* c,
                                        uint32_t a0, uint32_t a1, uint32_t a2, uint32_t a3,
                                        uint32_t b0, uint32_t b1) {
    asm volatile(
        "mma.sync.aligned.m16n8k16.row.col.f32.f16.f16.f32 "
        "{%0,%1,%2,%3}, {%4,%5,%6,%7}, {%8,%9}, {%0,%1,%2,%3};"
        : "+f"(c[0]), "+f"(c[1]), "+f"(c[2]), "+f"(c[3])
        : "r"(a0), "r"(a1), "r"(a2), "r"(a3), "r"(b0), "r"(b1));
}
__device__ __forceinline__ void ldsm4(uint32_t& r0, uint32_t& r1, uint32_t& r2,
                                      uint32_t& r3, uint32_t a) {
    asm volatile("ldmatrix.sync.aligned.m8n8.x4.shared.b16 {%0,%1,%2,%3}, [%4];"
                 : "=r"(r0), "=r"(r1), "=r"(r2), "=r"(r3) : "r"(a));
}
__device__ __forceinline__ void barg(int id) {
    asm volatile("bar.sync %0, 128;" :: "r"(id) : "memory");
}

// ---------------- pack kernel: W1/W2/W3 -> fp16 B-fragment layouts ----------------
__global__ void pack_kernel(const float* __restrict__ w1_w,
                            const float* __restrict__ w2_w,
                            const float* __restrict__ w3_w) {
    int idx = blockIdx.x * blockDim.x + threadIdx.x;   // 0 .. W1_FRAGS + W23_FRAGS - 1
    if (idx >= W1_FRAGS + W23_FRAGS) return;

    const float* src;
    uint2* dst;
    int kc, lane, nt;
    if (idx < W1_FRAGS) {             // W1: [nt(16)][kc(8)][lane(32)]
        lane = idx & 31; kc = (idx >> 5) & 7; nt = (idx >> 8) & 15;
        src = w1_w; dst = g_Wpack + idx;
    } else {                          // W2/W3: [p(2)][nt(16)][kc(8)][lane(32)]
        int i2 = idx - W1_FRAGS;
        lane = i2 & 31; kc = (i2 >> 5) & 7; nt = (i2 >> 8) & 15;
        int p = i2 >> 12;
        src = p ? w3_w : w2_w;
        dst = g_W23pack + i2;
    }
    int n  = nt * 8 + (lane >> 2);
    int k0 = kc * 16 + 2 * (lane & 3);
    const float* wr = src + n * I_DIM;
    uint2 v;
    v.x = pack_f16x2(wr[k0],     wr[k0 + 1]);
    v.y = pack_f16x2(wr[k0 + 8], wr[k0 + 9]);
    *dst = v;
}

// ---------------- main fused kernel ----------------
__global__ void __launch_bounds__(THREADS, 2)
fused_r8_kernel(const float* __restrict__ inputs,
                const int*   __restrict__ lengths,
                const float* __restrict__ w0,
                const float* __restrict__ w1_b,
                float* __restrict__ out)
{
    extern __shared__ float sm[];
    uint32_t* smu = reinterpret_cast<uint32_t*>(sm);

    const int tid   = threadIdx.x;
    const int lane  = tid & 31;
    const int wid   = tid >> 5;
    const int grp   = wid >> 2;      // group 0/1: alternating tiles
    const int nh    = wid & 3;       // h quarter (32 h = 4 n-tiles)
    const int g     = lane >> 2;     // row group 0..7
    const int qc    = lane & 3;      // col class 0..3
    const int local = tid & 127;     // index within group

    const int b     = blockIdx.x;
    const int len   = lengths[b];
    const int start = max(len - K_LAB, 0);
    const int nk    = min(len, K_LAB);

    // ---- copy packed W1 into smem (8192 words = 2048 uint4) ----
    uint4* wp4g = reinterpret_cast<uint4*>(g_Wpack);
    uint4* wp4s = reinterpret_cast<uint4*>(smu + SM_WP);
    #pragma unroll
    for (int i = 0; i < 8; i++)
        wp4s[tid + i * THREADS] = wp4g[tid + i * THREADS];
    const uint2* wp2 = reinterpret_cast<const uint2*>(smu + SM_WP);

    // ---- hoist w0 (pre-halved) / bias fragments ----
    float w0h[4][2], b1r[4][2];
    float w0s = 0.f;
    #pragma unroll
    for (int nt = 0; nt < 4; nt++)
        #pragma unroll
        for (int c = 0; c < 2; c++) {
            int h = nh * 32 + nt * 8 + 2 * qc + c;
            w0h[nt][c] = 0.5f * w0[h];
            w0s += w0h[nt][c];
            b1r[nt][c] = w1_b[h];
        }

    // ldmatrix lane address pattern (word offset within a buffer)
    const uint32_t arow = (uint32_t)((lane & 15) * XP + (lane >> 4) * 4);

    // ---- prefix partial sums: i = tid&127, parity q = tid>>7, MLP-8 ----
    {
        const int i = tid & 127;
        const int q = tid >> 7;
        const float* ip = inputs + (size_t)b * I_DIM + i;
        float a0 = 0.f, a1 = 0.f, a2 = 0.f, a3 = 0.f;
        int s = q;
        for (; s + 16 <= start; s += 16) {
            float v0 = ip[(size_t)(s     ) * BI];
            float v1 = ip[(size_t)(s +  2) * BI];
            float v2 = ip[(size_t)(s +  4) * BI];
            float v3 = ip[(size_t)(s +  6) * BI];
            float v4 = ip[(size_t)(s +  8) * BI];
            float v5 = ip[(size_t)(s + 10) * BI];
            float v6 = ip[(size_t)(s + 12) * BI];
            float v7 = ip[(size_t)(s + 14) * BI];
            a0 += v0 + v4; a1 += v1 + v5; a2 += v2 + v6; a3 += v3 + v7;
        }
        for (; s < start; s += 2)
            a0 += ip[(size_t)s * BI];
        sm[SM_PRE + q * 128 + i] = (a0 + a1) + (a2 + a3);
    }
    __syncthreads();

    // ---- labeled snapshots (tid < 128) ----
    if (tid < 128) {
        const int i = tid;
        const float* ip = inputs + (size_t)b * I_DIM + i;
        float acc = sm[SM_PRE + i] + sm[SM_PRE + 128 + i];
        #pragma unroll
        for (int k = 0; k < K_LAB; k++) {
            float xv = 0.f, mv = 0.f;
            if (k < nk) {
                xv = ip[(size_t)(start + k) * BI];
                acc += xv;
                mv = acc / (float)(start + k + 1);
            }
            sm[SM_XL + k * 128 + i] = xv;
            sm[SM_XM + k * 128 + i] = mv;
        }
    }
    __syncthreads();

    // ---- build c-phase A tile in XB buffer 0: rows 0-3 = xlab, 4-7 = xm, 8-15 = 0 ----
    {
        uint32_t* xh = smu + SM_XB;
        uint32_t* xl = xh + 2176;
        const int r   = tid >> 5;           // 0..7
        const int t32 = tid & 31;
        const float4 v = *reinterpret_cast<const float4*>(
            &sm[(r < 4 ? SM_XL + r * 128 : SM_XM + (r - 4) * 128) + t32 * 4]);
        uint32_t h0 = pack_f16x2(v.x, v.y);
        uint32_t h1 = pack_f16x2(v.z, v.w);
        float2 f0 = unpack_f16x2(h0);
        float2 f1 = unpack_f16x2(h1);
        uint32_t l0 = pack_f16x2(v.x - f0.x, v.y - f0.y);
        uint32_t l1 = pack_f16x2(v.z - f1.x, v.w - f1.y);
        int p = r * XP + t32 * 2;
        *reinterpret_cast<uint2*>(xh + p) = make_uint2(h0, h1);
        *reinterpret_cast<uint2*>(xl + p) = make_uint2(l0, l1);
        int z = (8 + r) * XP + t32 * 2;
        *reinterpret_cast<uint2*>(xh + z) = make_uint2(0u, 0u);
        *reinterpret_cast<uint2*>(xl + z) = make_uint2(0u, 0u);
    }
    __syncthreads();

    // ---- c[k][h] via MMA: pass0 B=W2 (-> x2), pass1 B=W3 (rows 4-7 -> wms) ----
    {
        const uint32_t ca_h = (uint32_t)__cvta_generic_to_shared(smu + SM_XB + arow);
        const uint32_t ca_l = ca_h + 2176 * 4;

        float acc1[2][4], acc2[2][4];
        #pragma unroll
        for (int j = 0; j < 2; j++)
            #pragma unroll
            for (int r = 0; r < 4; r++) { acc1[j][r] = 0.f; acc2[j][r] = 0.f; }

        #pragma unroll
        for (int p = 0; p < 2; p++) {
            float (*acc)[4] = p ? acc2 : acc1;
            #pragma unroll
            for (int kc = 0; kc < 8; kc++) {
                uint32_t ah0, ah1, ah2, ah3, al0, al1, al2, al3;
                ldsm4(ah0, ah1, ah2, ah3, ca_h + kc * 32);
                ldsm4(al0, al1, al2, al3, ca_l + kc * 32);
                #pragma unroll
                for (int j = 0; j < 2; j++) {
                    const int ntg = 2 * wid + j;
                    uint2 bq = g_W23pack[((p * 16 + ntg) * 8 + kc) * 32 + lane];
                    mma_f16(acc[j], ah0, ah1, ah2, ah3, bq.x, bq.y);
                    mma_f16(acc[j], al0, al1, al2, al3, bq.x, bq.y);
                }
            }
        }
        // extract: k = g (g<4), x2 = acc1 row g, wms = acc2 row g+4 (lane+16)
        #pragma unroll
        for (int j = 0; j < 2; j++)
            #pragma unroll
            for (int c2 = 0; c2 < 2; c2++) {
                float wmsv = __shfl_down_sync(0xffffffffu, acc2[j][c2], 16);
                if (g < 4) {
                    int h = (2 * wid + j) * 8 + 2 * qc + c2;
                    sm[SM_X2 + g * 128 + h] = acc1[j][c2];
                    sm[SM_CS + g * 128 + h] = acc1[j][c2] + wmsv;
                }
            }
    }
    __syncthreads();

    float hacc[K_LAB][4][2];
    #pragma unroll
    for (int k = 0; k < K_LAB; k++)
        #pragma unroll
        for (int nt = 0; nt < 4; nt++) { hacc[k][nt][0] = 0.f; hacc[k][nt][1] = 0.f; }

    const int n_tiles = (len + S_TILE - 1) >> 5;
    uint32_t* xh = smu + SM_XB + grp * BUFW;
    uint32_t* xl = xh + 2176;
    float*    pbg = sm + SM_PB + grp * 512;
    const int bar = 1 + grp;

    const uint32_t sa_h = (uint32_t)__cvta_generic_to_shared(xh + arow);
    const uint32_t sa_l = sa_h + 2176 * 4;

    const int srow = local >> 2;     // staging row 0..31 (4 threads/row)
    const int f4c  = local & 3;

    // ================= group tile loop (t = grp, grp+2, ...) =================
    for (int t = grp; t < n_tiles; t += 2) {
        const int s0 = t * S_TILE;

        // ---- stage: coalesced LDG + fp16 hi/lo convert + STS into group buffer ----
        {
            const int gs = s0 + srow;
            const bool vld = (gs < len);
            const float4* src = reinterpret_cast<const float4*>(
                inputs + (size_t)gs * BI + (size_t)b * I_DIM);
            #pragma unroll
            for (int j = 0; j < 8; j++) {
                const int c4 = j * 4 + f4c;          // coalesced per j
                float4 x = vld ? src[c4] : make_float4(0.f, 0.f, 0.f, 0.f);
                uint32_t h0 = pack_f16x2(x.x, x.y);
                uint32_t h1 = pack_f16x2(x.z, x.w);
                float2 f0 = unpack_f16x2(h0);
                float2 f1 = unpack_f16x2(h1);
                uint32_t l0 = pack_f16x2(x.x - f0.x, x.y - f0.y);
                uint32_t l1 = pack_f16x2(x.z - f1.x, x.w - f1.y);
                int p = srow * XP + c4 * 2;
                *reinterpret_cast<uint2*>(xh + p) = make_uint2(h0, h1);
                *reinterpret_cast<uint2*>(xl + p) = make_uint2(l0, l1);
            }
        }
        barg(bar);

        // ---- 2-pass fp16 MMA: warp tile 32s x 32h, A-frags via ldmatrix ----
        float x1f[2][4][4];
        #pragma unroll
        for (int mt = 0; mt < 2; mt++)
            #pragma unroll
            for (int nt = 0; nt < 4; nt++)
                #pragma unroll
                for (int r = 0; r < 4; r++) x1f[mt][nt][r] = 0.f;

        #pragma unroll
        for (int kc = 0; kc < 8; kc++) {
            uint32_t ah[2][4], al[2][4];
            #pragma unroll
            for (int mt = 0; mt < 2; mt++) {
                const uint32_t off = (uint32_t)(mt * 16 * XP * 4 + kc * 32);
                ldsm4(ah[mt][0], ah[mt][1], ah[mt][2], ah[mt][3], sa_h + off);
                ldsm4(al[mt][0], al[mt][1], al[mt][2], al[mt][3], sa_l + off);
            }
            #pragma unroll
            for (int nt = 0; nt < 4; nt++) {
                uint2 bq = wp2[((nh * 4 + nt) * 8 + kc) * 32 + lane];
                #pragma unroll
                for (int mt = 0; mt < 2; mt++) {
                    mma_f16(x1f[mt][nt], ah[mt][0], ah[mt][1], ah[mt][2], ah[mt][3], bq.x, bq.y);
                    mma_f16(x1f[mt][nt], al[mt][0], al[mt][1], al[mt][2], al[mt][3], bq.x, bq.y);
                }
            }
        }
        #pragma unroll
        for (int mt = 0; mt < 2; mt++)
            #pragma unroll
            for (int nt = 0; nt < 4; nt++) {
                x1f[mt][nt][0] += b1r[nt][0];
                x1f[mt][nt][1] += b1r[nt][1];
                x1f[mt][nt][2] += b1r[nt][0];
                x1f[mt][nt][3] += b1r[nt][1];
            }

        // ---- sigmoid (tanh form) + w0 partial sums ----
        #pragma unroll
        for (int k = 0; k < K_LAB; k++) {
            const int tk = start + k;
            if (k < nk && s0 <= tk) {
                float ps[2][2];
                ps[0][0] = w0s; ps[0][1] = w0s; ps[1][0] = w0s; ps[1][1] = w0s;
                #pragma unroll
                for (int nt = 0; nt < 4; nt++) {
                    float2 cv = *reinterpret_cast<const float2*>(
                        &sm[SM_CS + k * 128 + nh * 32 + nt * 8 + 2 * qc]);
                    #pragma unroll
                    for (int mt = 0; mt < 2; mt++) {
                        ps[mt][0] += w0h[nt][0] * tanhf_fast(0.5f * (x1f[mt][nt][0] + cv.x))
                                   + w0h[nt][1] * tanhf_fast(0.5f * (x1f[mt][nt][1] + cv.y));
                        ps[mt][1] += w0h[nt][0] * tanhf_fast(0.5f * (x1f[mt][nt][2] + cv.x))
                                   + w0h[nt][1] * tanhf_fast(0.5f * (x1f[mt][nt][3] + cv.y));
                    }
                }
                #pragma unroll
                for (int mt = 0; mt < 2; mt++)
                    #pragma unroll
                    for (int r = 0; r < 2; r++) {
                        float v = ps[mt][r];
                        v += __shfl_xor_sync(0xffffffffu, v, 1);
                        v += __shfl_xor_sync(0xffffffffu, v, 2);
                        ps[mt][r] = v;
                    }
                if (qc == 0) {
                    #pragma unroll
                    for (int mt = 0; mt < 2; mt++) {
                        pbg[(k * 32 + mt * 16 + g) * 4 + nh]     = ps[mt][0];
                        pbg[(k * 32 + mt * 16 + g + 8) * 4 + nh] = ps[mt][1];
                    }
                }
            }
        }
        barg(bar);

        // ---- read total p, mask, accumulate h ----
        const float4* pb4 = reinterpret_cast<const float4*>(pbg);
        #pragma unroll
        for (int k = 0; k < K_LAB; k++) {
            const int tk = start + k;
            if (k < nk && s0 <= tk) {
                #pragma unroll
                for (int mt = 0; mt < 2; mt++) {
                    const int r0 = mt * 16 + g;
                    float4 p0 = pb4[k * 32 + r0];
                    float4 p1 = pb4[k * 32 + r0 + 8];
                    float pt0 = (s0 + r0     <= tk) ? (p0.x + p0.y + p0.z + p0.w) : 0.f;
                    float pt1 = (s0 + r0 + 8 <= tk) ? (p1.x + p1.y + p1.z + p1.w) : 0.f;
                    #pragma unroll
                    for (int nt = 0; nt < 4; nt++) {
                        hacc[k][nt][0] += pt0 * x1f[mt][nt][0] + pt1 * x1f[mt][nt][2];
                        hacc[k][nt][1] += pt0 * x1f[mt][nt][1] + pt1 * x1f[mt][nt][3];
                    }
                }
            }
        }
        // next PB write only happens after the next barg(bar) -> safe
    }

    // ---- reduce hacc over row groups, stash per-group partials (HB overlays XB) ----
    __syncthreads();   // both groups done with buffers
    #pragma unroll
    for (int k = 0; k < K_LAB; k++)
        #pragma unroll
        for (int nt = 0; nt < 4; nt++)
            #pragma unroll
            for (int c = 0; c < 2; c++) {
                float v = hacc[k][nt][c];
                v += __shfl_xor_sync(0xffffffffu, v, 4);
                v += __shfl_xor_sync(0xffffffffu, v, 8);
                v += __shfl_xor_sync(0xffffffffu, v, 16);
                if (g == 0)
                    sm[SM_HB + (grp * 4 + k) * 128 + nh * 32 + nt * 8 + 2 * qc + c] = v;
            }
    __syncthreads();

    // ---- final output ----
    #pragma unroll
    for (int jj = 0; jj < 2; jj++) {
        int idx = tid + jj * THREADS;   // 0..511
        int k = idx >> 7, h = idx & 127;
        float v = 0.f;
        if (k < nk)
            v = sm[SM_HB + k * 128 + h] + sm[SM_HB + (4 + k) * 128 + h]
              + sm[SM_X2 + k * 128 + h];
        out[(size_t)b * (K_LAB * H_DIM) + idx] = v;
    }
}

extern "C" void kernel_launch(void* const* d_in, const int* in_sizes, int n_in,
                              void* d_out, int out_size)
{
    // input order: inputs, lengths, [label_len], w0, w1_w, w1_b, w2_w, w3_w
    const int base = (n_in >= 8) ? 3 : 2;
    const float* inputs  = (const float*)d_in[0];
    const int*   lengths = (const int*)d_in[1];
    const float* w0   = (const float*)d_in[base + 0];
    const float* w1_w = (const float*)d_in[base + 1];
    const float* w1_b = (const float*)d_in[base + 2];
    const float* w2_w = (const float*)d_in[base + 3];
    const float* w3_w = (const float*)d_in[base + 4];
    float* out = (float*)d_out;

    pack_kernel<<<48, 256>>>(w1_w, w2_w, w3_w);   // 12288 entries

    const size_t smem_bytes = (size_t)SM_TOT * sizeof(float);
    cudaFuncSetAttribute(fused_r8_kernel,
                         cudaFuncAttributeMaxDynamicSharedMemorySize,
                         (int)smem_bytes);
    fused_r8_kernel<<<GRID, THREADS, smem_bytes>>>(inputs, lengths, w0, w1_b, out);
}

// round 9
// speedup vs baseline: 4.2977x; 1.1162x over previous
#include <cuda_runtime.h>
#include <cuda_fp16.h>
#include <cstdint>

#define T_DIM 200
#define B_DIM 2048
#define I_DIM 128
#define H_DIM 128
#define K_LAB 4
#define S_TILE 32
#define GRID   2048
#define THREADS 256
#define XP     68             // pair-row stride (u32 words): conflict-free A-frag reads
#define BI     (B_DIM * I_DIM)

// ---- shared memory layout (4-byte word offsets) ----
#define SM_WP   0                  // 16*8*32 uint2 = 8192 words (32 KB W1 pack, fp16)
#define SM_XB   8192               // per-group staging buffer (hi only)
#define BUFW    2176               // words per group buffer (32 rows * 68)
#define SM_PB   (SM_XB + 2*BUFW)   // 12544: per-group p exchange, 2 * 512
#define SM_CS   (SM_PB + 1024)     // 13568
#define SM_X2   (SM_CS + 512)      // 14080
#define SM_XL   (SM_X2 + 512)      // 14592
#define SM_XM   (SM_XL + 512)      // 15104
#define SM_PRE  (SM_XM + 512)      // 15616
#define SM_HB   SM_XB              // reused after tile loop: 2grp*4k*128 = 1024
#define SM_TOT  (SM_PRE + 256)     // 15872 words = 63488 B

#define W1_FRAGS  (16 * 8 * 32)    // 4096
#define W23_FRAGS (2 * 16 * 8 * 32)

// W1 packed as fp16 B fragments: [nt(16)][kc(8)][lane(32)] -> (wh0, wh1)
__device__ uint2 g_Wpack[W1_FRAGS];
// W2 (pass 0) and W3 (pass 1) packed the same way: [p(2)][nt(16)][kc(8)][lane(32)]
__device__ uint2 g_W23pack[W23_FRAGS];

__device__ __forceinline__ uint32_t pack_f16x2(float e_even, float e_odd) {
    uint32_t r;
    asm("cvt.rn.f16x2.f32 %0, %1, %2;" : "=r"(r) : "f"(e_odd), "f"(e_even));
    return r;
}
__device__ __forceinline__ float2 unpack_f16x2(uint32_t u) {
    __half2 h = *reinterpret_cast<__half2*>(&u);
    return __half22float2(h);
}

__device__ __forceinline__ float tanhf_fast(float z) {
    float t;
    asm("tanh.approx.f32 %0, %1;" : "=f"(t) : "f"(z));
    return t;
}
__device__ __forceinline__ void mma_f16(float* c,
                                        uint32_t a0, uint32_t a1, uint32_t a2, uint32_t a3,
                                        uint32_t b0, uint32_t b1) {
    asm volatile(
        "mma.sync.aligned.m16n8k16.row.col.f32.f16.f16.f32 "
        "{%0,%1,%2,%3}, {%4,%5,%6,%7}, {%8,%9}, {%0,%1,%2,%3};"
        : "+f"(c[0]), "+f"(c[1]), "+f"(c[2]), "+f"(c[3])
        : "r"(a0), "r"(a1), "r"(a2), "r"(a3), "r"(b0), "r"(b1));
}
__device__ __forceinline__ void ldsm4(uint32_t& r0, uint32_t& r1, uint32_t& r2,
                                      uint32_t& r3, uint32_t a) {
    asm volatile("ldmatrix.sync.aligned.m8n8.x4.shared.b16 {%0,%1,%2,%3}, [%4];"
                 : "=r"(r0), "=r"(r1), "=r"(r2), "=r"(r3) : "r"(a));
}
__device__ __forceinline__ void barg(int id) {
    asm volatile("bar.sync %0, 128;" :: "r"(id) : "memory");
}

// ---------------- pack kernel: W1/W2/W3 -> fp16 B-fragment layouts ----------------
__global__ void pack_kernel(const float* __restrict__ w1_w,
                            const float* __restrict__ w2_w,
                            const float* __restrict__ w3_w) {
    int idx = blockIdx.x * blockDim.x + threadIdx.x;   // 0 .. W1_FRAGS + W23_FRAGS - 1
    if (idx >= W1_FRAGS + W23_FRAGS) return;

    const float* src;
    uint2* dst;
    int kc, lane, nt;
    if (idx < W1_FRAGS) {             // W1: [nt(16)][kc(8)][lane(32)]
        lane = idx & 31; kc = (idx >> 5) & 7; nt = (idx >> 8) & 15;
        src = w1_w; dst = g_Wpack + idx;
    } else {                          // W2/W3: [p(2)][nt(16)][kc(8)][lane(32)]
        int i2 = idx - W1_FRAGS;
        lane = i2 & 31; kc = (i2 >> 5) & 7; nt = (i2 >> 8) & 15;
        int p = i2 >> 12;
        src = p ? w3_w : w2_w;
        dst = g_W23pack + i2;
    }
    int n  = nt * 8 + (lane >> 2);
    int k0 = kc * 16 + 2 * (lane & 3);
    const float* wr = src + n * I_DIM;
    uint2 v;
    v.x = pack_f16x2(wr[k0],     wr[k0 + 1]);
    v.y = pack_f16x2(wr[k0 + 8], wr[k0 + 9]);
    *dst = v;
}

// ---------------- main fused kernel ----------------
__global__ void __launch_bounds__(THREADS, 2)
fused_r9_kernel(const float* __restrict__ inputs,
                const int*   __restrict__ lengths,
                const float* __restrict__ w0,
                const float* __restrict__ w1_b,
                float* __restrict__ out)
{
    extern __shared__ float sm[];
    uint32_t* smu = reinterpret_cast<uint32_t*>(sm);

    const int tid   = threadIdx.x;
    const int lane  = tid & 31;
    const int wid   = tid >> 5;
    const int grp   = wid >> 2;      // group 0/1: alternating tiles
    const int nh    = wid & 3;       // h quarter (32 h = 4 n-tiles)
    const int g     = lane >> 2;     // row group 0..7
    const int qc    = lane & 3;      // col class 0..3
    const int local = tid & 127;     // index within group

    const int b     = blockIdx.x;
    const int len   = lengths[b];
    const int start = max(len - K_LAB, 0);
    const int nk    = min(len, K_LAB);

    // ---- copy packed W1 into smem (8192 words = 2048 uint4) ----
    uint4* wp4g = reinterpret_cast<uint4*>(g_Wpack);
    uint4* wp4s = reinterpret_cast<uint4*>(smu + SM_WP);
    #pragma unroll
    for (int i = 0; i < 8; i++)
        wp4s[tid + i * THREADS] = wp4g[tid + i * THREADS];
    const uint2* wp2 = reinterpret_cast<const uint2*>(smu + SM_WP);

    // ---- hoist w0 (pre-halved) / bias fragments ----
    float w0h[4][2], b1r[4][2];
    float w0s = 0.f;
    #pragma unroll
    for (int nt = 0; nt < 4; nt++)
        #pragma unroll
        for (int c = 0; c < 2; c++) {
            int h = nh * 32 + nt * 8 + 2 * qc + c;
            w0h[nt][c] = 0.5f * w0[h];
            w0s += w0h[nt][c];
            b1r[nt][c] = w1_b[h];
        }

    // ldmatrix lane address pattern (word offset within a buffer)
    const uint32_t arow = (uint32_t)((lane & 15) * XP + (lane >> 4) * 4);

    // ---- prefix partial sums: i = tid&127, parity q = tid>>7, MLP-8 ----
    {
        const int i = tid & 127;
        const int q = tid >> 7;
        const float* ip = inputs + (size_t)b * I_DIM + i;
        float a0 = 0.f, a1 = 0.f, a2 = 0.f, a3 = 0.f;
        int s = q;
        for (; s + 16 <= start; s += 16) {
            float v0 = ip[(size_t)(s     ) * BI];
            float v1 = ip[(size_t)(s +  2) * BI];
            float v2 = ip[(size_t)(s +  4) * BI];
            float v3 = ip[(size_t)(s +  6) * BI];
            float v4 = ip[(size_t)(s +  8) * BI];
            float v5 = ip[(size_t)(s + 10) * BI];
            float v6 = ip[(size_t)(s + 12) * BI];
            float v7 = ip[(size_t)(s + 14) * BI];
            a0 += v0 + v4; a1 += v1 + v5; a2 += v2 + v6; a3 += v3 + v7;
        }
        for (; s < start; s += 2)
            a0 += ip[(size_t)s * BI];
        sm[SM_PRE + q * 128 + i] = (a0 + a1) + (a2 + a3);
    }
    __syncthreads();

    // ---- labeled snapshots (tid < 128) ----
    if (tid < 128) {
        const int i = tid;
        const float* ip = inputs + (size_t)b * I_DIM + i;
        float acc = sm[SM_PRE + i] + sm[SM_PRE + 128 + i];
        #pragma unroll
        for (int k = 0; k < K_LAB; k++) {
            float xv = 0.f, mv = 0.f;
            if (k < nk) {
                xv = ip[(size_t)(start + k) * BI];
                acc += xv;
                mv = acc / (float)(start + k + 1);
            }
            sm[SM_XL + k * 128 + i] = xv;
            sm[SM_XM + k * 128 + i] = mv;
        }
    }
    __syncthreads();

    // ---- build c-phase A tile: hi in grp0 buffer, lo in grp1 buffer ----
    // rows 0-3 = xlab, 4-7 = xm, 8-15 = 0
    {
        uint32_t* xh = smu + SM_XB;            // buffer 0 (hi)
        uint32_t* xl = smu + SM_XB + BUFW;     // buffer 1 (lo)
        const int r   = tid >> 5;           // 0..7
        const int t32 = tid & 31;
        const float4 v = *reinterpret_cast<const float4*>(
            &sm[(r < 4 ? SM_XL + r * 128 : SM_XM + (r - 4) * 128) + t32 * 4]);
        uint32_t h0 = pack_f16x2(v.x, v.y);
        uint32_t h1 = pack_f16x2(v.z, v.w);
        float2 f0 = unpack_f16x2(h0);
        float2 f1 = unpack_f16x2(h1);
        uint32_t l0 = pack_f16x2(v.x - f0.x, v.y - f0.y);
        uint32_t l1 = pack_f16x2(v.z - f1.x, v.w - f1.y);
        int p = r * XP + t32 * 2;
        *reinterpret_cast<uint2*>(xh + p) = make_uint2(h0, h1);
        *reinterpret_cast<uint2*>(xl + p) = make_uint2(l0, l1);
        int z = (8 + r) * XP + t32 * 2;
        *reinterpret_cast<uint2*>(xh + z) = make_uint2(0u, 0u);
        *reinterpret_cast<uint2*>(xl + z) = make_uint2(0u, 0u);
    }
    __syncthreads();

    // ---- c[k][h] via MMA (2-pass hi/lo A): pass0 B=W2 (-> x2), pass1 B=W3 (rows 4-7 -> wms) ----
    {
        const uint32_t ca_h = (uint32_t)__cvta_generic_to_shared(smu + SM_XB + arow);
        const uint32_t ca_l = ca_h + BUFW * 4;

        float acc1[2][4], acc2[2][4];
        #pragma unroll
        for (int j = 0; j < 2; j++)
            #pragma unroll
            for (int r = 0; r < 4; r++) { acc1[j][r] = 0.f; acc2[j][r] = 0.f; }

        #pragma unroll
        for (int p = 0; p < 2; p++) {
            float (*acc)[4] = p ? acc2 : acc1;
            #pragma unroll
            for (int kc = 0; kc < 8; kc++) {
                uint32_t ah0, ah1, ah2, ah3, al0, al1, al2, al3;
                ldsm4(ah0, ah1, ah2, ah3, ca_h + kc * 32);
                ldsm4(al0, al1, al2, al3, ca_l + kc * 32);
                #pragma unroll
                for (int j = 0; j < 2; j++) {
                    const int ntg = 2 * wid + j;
                    uint2 bq = g_W23pack[((p * 16 + ntg) * 8 + kc) * 32 + lane];
                    mma_f16(acc[j], ah0, ah1, ah2, ah3, bq.x, bq.y);
                    mma_f16(acc[j], al0, al1, al2, al3, bq.x, bq.y);
                }
            }
        }
        // extract: k = g (g<4), x2 = acc1 row g, wms = acc2 row g+4 (lane+16)
        #pragma unroll
        for (int j = 0; j < 2; j++)
            #pragma unroll
            for (int c2 = 0; c2 < 2; c2++) {
                float wmsv = __shfl_down_sync(0xffffffffu, acc2[j][c2], 16);
                if (g < 4) {
                    int h = (2 * wid + j) * 8 + 2 * qc + c2;
                    sm[SM_X2 + g * 128 + h] = acc1[j][c2];
                    sm[SM_CS + g * 128 + h] = acc1[j][c2] + wmsv;
                }
            }
    }
    __syncthreads();

    float hacc[K_LAB][4][2];
    #pragma unroll
    for (int k = 0; k < K_LAB; k++)
        #pragma unroll
        for (int nt = 0; nt < 4; nt++) { hacc[k][nt][0] = 0.f; hacc[k][nt][1] = 0.f; }

    const int n_tiles = (len + S_TILE - 1) >> 5;
    uint32_t* xh = smu + SM_XB + grp * BUFW;
    float*    pbg = sm + SM_PB + grp * 512;
    const int bar = 1 + grp;

    const uint32_t sa_h = (uint32_t)__cvta_generic_to_shared(xh + arow);

    const int srow = local >> 2;     // staging row 0..31 (4 threads/row)
    const int f4c  = local & 3;

    // ================= group tile loop (t = grp, grp+2, ...) =================
    for (int t = grp; t < n_tiles; t += 2) {
        const int s0 = t * S_TILE;

        // ---- stage: coalesced LDG + single fp16 convert + STS into group buffer ----
        {
            const int gs = s0 + srow;
            const bool vld = (gs < len);
            const float4* src = reinterpret_cast<const float4*>(
                inputs + (size_t)gs * BI + (size_t)b * I_DIM);
            #pragma unroll
            for (int j = 0; j < 8; j++) {
                const int c4 = j * 4 + f4c;          // coalesced per j
                float4 x = vld ? src[c4] : make_float4(0.f, 0.f, 0.f, 0.f);
                uint32_t h0 = pack_f16x2(x.x, x.y);
                uint32_t h1 = pack_f16x2(x.z, x.w);
                *reinterpret_cast<uint2*>(xh + srow * XP + c4 * 2) = make_uint2(h0, h1);
            }
        }
        barg(bar);

        // ---- single-pass fp16 MMA: warp tile 32s x 32h, A-frags via ldmatrix ----
        float x1f[2][4][4];
        #pragma unroll
        for (int mt = 0; mt < 2; mt++)
            #pragma unroll
            for (int nt = 0; nt < 4; nt++)
                #pragma unroll
                for (int r = 0; r < 4; r++) x1f[mt][nt][r] = 0.f;

        #pragma unroll
        for (int kc = 0; kc < 8; kc++) {
            uint32_t ah[2][4];
            #pragma unroll
            for (int mt = 0; mt < 2; mt++) {
                const uint32_t off = (uint32_t)(mt * 16 * XP * 4 + kc * 32);
                ldsm4(ah[mt][0], ah[mt][1], ah[mt][2], ah[mt][3], sa_h + off);
            }
            #pragma unroll
            for (int nt = 0; nt < 4; nt++) {
                uint2 bq = wp2[((nh * 4 + nt) * 8 + kc) * 32 + lane];
                #pragma unroll
                for (int mt = 0; mt < 2; mt++)
                    mma_f16(x1f[mt][nt], ah[mt][0], ah[mt][1], ah[mt][2], ah[mt][3], bq.x, bq.y);
            }
        }
        #pragma unroll
        for (int mt = 0; mt < 2; mt++)
            #pragma unroll
            for (int nt = 0; nt < 4; nt++) {
                x1f[mt][nt][0] += b1r[nt][0];
                x1f[mt][nt][1] += b1r[nt][1];
                x1f[mt][nt][2] += b1r[nt][0];
                x1f[mt][nt][3] += b1r[nt][1];
            }

        // ---- sigmoid (tanh form) + w0 partial sums ----
        #pragma unroll
        for (int k = 0; k < K_LAB; k++) {
            const int tk = start + k;
            if (k < nk && s0 <= tk) {
                float ps[2][2];
                ps[0][0] = w0s; ps[0][1] = w0s; ps[1][0] = w0s; ps[1][1] = w0s;
                #pragma unroll
                for (int nt = 0; nt < 4; nt++) {
                    float2 cv = *reinterpret_cast<const float2*>(
                        &sm[SM_CS + k * 128 + nh * 32 + nt * 8 + 2 * qc]);
                    #pragma unroll
                    for (int mt = 0; mt < 2; mt++) {
                        ps[mt][0] += w0h[nt][0] * tanhf_fast(0.5f * (x1f[mt][nt][0] + cv.x))
                                   + w0h[nt][1] * tanhf_fast(0.5f * (x1f[mt][nt][1] + cv.y));
                        ps[mt][1] += w0h[nt][0] * tanhf_fast(0.5f * (x1f[mt][nt][2] + cv.x))
                                   + w0h[nt][1] * tanhf_fast(0.5f * (x1f[mt][nt][3] + cv.y));
                    }
                }
                #pragma unroll
                for (int mt = 0; mt < 2; mt++)
                    #pragma unroll
                    for (int r = 0; r < 2; r++) {
                        float v = ps[mt][r];
                        v += __shfl_xor_sync(0xffffffffu, v, 1);
                        v += __shfl_xor_sync(0xffffffffu, v, 2);
                        ps[mt][r] = v;
                    }
                if (qc == 0) {
                    #pragma unroll
                    for (int mt = 0; mt < 2; mt++) {
                        pbg[(k * 32 + mt * 16 + g) * 4 + nh]     = ps[mt][0];
                        pbg[(k * 32 + mt * 16 + g + 8) * 4 + nh] = ps[mt][1];
                    }
                }
            }
        }
        barg(bar);

        // ---- read total p, mask, accumulate h ----
        const float4* pb4 = reinterpret_cast<const float4*>(pbg);
        #pragma unroll
        for (int k = 0; k < K_LAB; k++) {
            const int tk = start + k;
            if (k < nk && s0 <= tk) {
                #pragma unroll
                for (int mt = 0; mt < 2; mt++) {
                    const int r0 = mt * 16 + g;
                    float4 p0 = pb4[k * 32 + r0];
                    float4 p1 = pb4[k * 32 + r0 + 8];
                    float pt0 = (s0 + r0     <= tk) ? (p0.x + p0.y + p0.z + p0.w) : 0.f;
                    float pt1 = (s0 + r0 + 8 <= tk) ? (p1.x + p1.y + p1.z + p1.w) : 0.f;
                    #pragma unroll
                    for (int nt = 0; nt < 4; nt++) {
                        hacc[k][nt][0] += pt0 * x1f[mt][nt][0] + pt1 * x1f[mt][nt][2];
                        hacc[k][nt][1] += pt0 * x1f[mt][nt][1] + pt1 * x1f[mt][nt][3];
                    }
                }
            }
        }
        // next PB write only happens after the next barg(bar) -> safe
    }

    // ---- reduce hacc over row groups, stash per-group partials (HB overlays XB) ----
    __syncthreads();   // both groups done with buffers
    #pragma unroll
    for (int k = 0; k < K_LAB; k++)
        #pragma unroll
        for (int nt = 0; nt < 4; nt++)
            #pragma unroll
            for (int c = 0; c < 2; c++) {
                float v = hacc[k][nt][c];
                v += __shfl_xor_sync(0xffffffffu, v, 4);
                v += __shfl_xor_sync(0xffffffffu, v, 8);
                v += __shfl_xor_sync(0xffffffffu, v, 16);
                if (g == 0)
                    sm[SM_HB + (grp * 4 + k) * 128 + nh * 32 + nt * 8 + 2 * qc + c] = v;
            }
    __syncthreads();

    // ---- final output ----
    #pragma unroll
    for (int jj = 0; jj < 2; jj++) {
        int idx = tid + jj * THREADS;   // 0..511
        int k = idx >> 7, h = idx & 127;
        float v = 0.f;
        if (k < nk)
            v = sm[SM_HB + k * 128 + h] + sm[SM_HB + (4 + k) * 128 + h]
              + sm[SM_X2 + k * 128 + h];
        out[(size_t)b * (K_LAB * H_DIM) + idx] = v;
    }
}

extern "C" void kernel_launch(void* const* d_in, const int* in_sizes, int n_in,
                              void* d_out, int out_size)
{
    // input order: inputs, lengths, [label_len], w0, w1_w, w1_b, w2_w, w3_w
    const int base = (n_in >= 8) ? 3 : 2;
    const float* inputs  = (const float*)d_in[0];
    const int*   lengths = (const int*)d_in[1];
    const float* w0   = (const float*)d_in[base + 0];
    const float* w1_w = (const float*)d_in[base + 1];
    const float* w1_b = (const float*)d_in[base + 2];
    const float* w2_w = (const float*)d_in[base + 3];
    const float* w3_w = (const float*)d_in[base + 4];
    float* out = (float*)d_out;

    pack_kernel<<<48, 256>>>(w1_w, w2_w, w3_w);   // 12288 entries

    const size_t smem_bytes = (size_t)SM_TOT * sizeof(float);
    cudaFuncSetAttribute(fused_r9_kernel,
                         cudaFuncAttributeMaxDynamicSharedMemorySize,
                         (int)smem_bytes);
    fused_r9_kernel<<<GRID, THREADS, smem_bytes>>>(inputs, lengths, w0, w1_b, out);
}